// round 9
// baseline (speedup 1.0000x reference)
#include <cuda_runtime.h>
#include <math.h>
#include <stdint.h>

// N=50000, P=1.6M, F=128, G=16, H=32, HID1=256, HID2=128, IN=288 (vec_q==0 dropped)
#define NMAX 50000

__device__ float g_acc[NMAX * 64];            // [n][0:16]=Gsum, [16:64]=GVsum(d,g)
__device__ float g_msg[(size_t)NMAX * 288];   // MLP input, tf32-rounded
__device__ float g_embT[(size_t)NMAX * 128];  // emb tf32; reused as H2 after gemm
__device__ float g_h1[(size_t)NMAX * 256];    // layer1 activations (tf32-rounded)
__device__ float g_aghT[128 * 512];           // agh tf32
__device__ float g_w1t[288 * 256];            // W1 tf32
__device__ float g_w2t[256 * 128];            // W2 tf32
__device__ float g_w3t[128 * 136];            // W3 tf32, cols padded 130->136 (zeros)

__device__ __forceinline__ float gelu_exact(float x) {
    return 0.5f * x * (1.0f + erff(x * 0.70710678118654752f));
}
__device__ __forceinline__ float f2tf(float x) {
    uint32_t r;
    asm("cvt.rna.tf32.f32 %0, %1;" : "=r"(r) : "f"(x));
    return __uint_as_float(r);
}
__device__ __forceinline__ void mma_tf32(float d[4], const uint32_t a[4],
                                         const uint32_t b[2]) {
    asm volatile(
        "mma.sync.aligned.m16n8k8.row.col.f32.tf32.tf32.f32 "
        "{%0,%1,%2,%3}, {%4,%5,%6,%7}, {%8,%9}, {%0,%1,%2,%3};"
        : "+f"(d[0]), "+f"(d[1]), "+f"(d[2]), "+f"(d[3])
        : "r"(a[0]), "r"(a[1]), "r"(a[2]), "r"(a[3]), "r"(b[0]), "r"(b[1]));
}
__device__ __forceinline__ uint32_t fu(float x) { return __float_as_uint(x); }

__device__ __forceinline__ void cpa16(float* s, const float* g) {
    uint32_t sp = (uint32_t)__cvta_generic_to_shared(s);
    asm volatile("cp.async.cg.shared.global [%0], [%1], 16;" :: "r"(sp), "l"(g));
}
#define CP_COMMIT() asm volatile("cp.async.commit_group;" ::: "memory")
#define CP_WAIT1()  asm volatile("cp.async.wait_group 1;" ::: "memory")
#define CP_WAIT0()  asm volatile("cp.async.wait_group 0;" ::: "memory")

// ---------------------------------------------------------------------------
// Launch 1: tf32 pre-conversion (weights + emb) AND zero pair accumulators
// ---------------------------------------------------------------------------
#define CVT_W (128 * 512 + 288 * 256 + 256 * 128 + 128 * 136)
__global__ void k_cvt(const float* __restrict__ agh, const float* __restrict__ W1,
                      const float* __restrict__ W2, const float* __restrict__ W3,
                      const float* __restrict__ emb, int N) {
    int i = blockIdx.x * blockDim.x + threadIdx.x;
    if (i < 128 * 512) { g_aghT[i] = f2tf(agh[i]); return; }
    i -= 128 * 512;
    if (i < 288 * 256) { g_w1t[i] = f2tf(W1[i]); return; }
    i -= 288 * 256;
    if (i < 256 * 128) { g_w2t[i] = f2tf(W2[i]); return; }
    i -= 256 * 128;
    if (i < 128 * 136) {
        int r = i / 136, c = i - r * 136;
        g_w3t[i] = (c < 130) ? f2tf(W3[r * 130 + c]) : 0.f;
        return;
    }
    i -= 128 * 136;
    if (i < N * 32) {
        float4 v = reinterpret_cast<const float4*>(emb)[i];
        float4 o = make_float4(f2tf(v.x), f2tf(v.y), f2tf(v.z), f2tf(v.w));
        reinterpret_cast<float4*>(g_embT)[i] = o;
        return;
    }
    i -= N * 32;
    if (i < N * 16)
        reinterpret_cast<float4*>(g_acc)[i] = make_float4(0.f, 0.f, 0.f, 0.f);
}

// ---------------------------------------------------------------------------
// Launch 2: scatter gs(16)+gv(48) per pair via red.global.add.v4 (unchanged)
// ---------------------------------------------------------------------------
__global__ void k_scatter(const int* __restrict__ idxj, const float* __restrict__ gs,
                          const float* __restrict__ gv, int P) {
    long long q = (long long)blockIdx.x * blockDim.x + threadIdx.x;
    long long total = (long long)P * 16;
    if (q >= total) return;
    int p = (int)(q >> 4);
    int c = (int)(q & 15);
    int n = idxj[p];
    float4 v;
    float* dst;
    if (c < 4) {
        v = *reinterpret_cast<const float4*>(gs + (size_t)p * 16 + c * 4);
        dst = g_acc + (size_t)n * 64 + c * 4;
    } else {
        v = *reinterpret_cast<const float4*>(gv + (size_t)p * 48 + (c - 4) * 4);
        dst = g_acc + (size_t)n * 64 + 16 + (c - 4) * 4;
    }
    asm volatile("red.global.add.v4.f32 [%0], {%1,%2,%3,%4};"
                 :: "l"(dst), "f"(v.x), "f"(v.y), "f"(v.z), "f"(v.w)
                 : "memory");
}

// ---------------------------------------------------------------------------
// Launch 3: fused GEMM-M + assemble (unchanged from R6-R8, 90us known-good).
// ---------------------------------------------------------------------------
#define XSF 132
#define WSC 520
#define MSF 516
#define OXS 0
#define OSA 4224
#define OWG 6272
#define OWB 8320
#define GA_SMEM (24960 * 4)           // 99840 B

__global__ void __launch_bounds__(256, 2) k_gemm_assemble(
    const float* __restrict__ q, const float* __restrict__ Wgf, int N) {
    extern __shared__ float sm[];
    float* Xs   = sm + OXS;
    float* sa   = sm + OSA;
    float* Wgfs = sm + OWG;
    float* Wb0  = sm + OWB;
    float* Wb1  = sm + OWB + 8320;
    float* Ms   = sm + OWB;
    int a0 = blockIdx.x * 32;
    int tid = threadIdx.x;
    int lane = tid & 31, wn = tid >> 5;
    int gid = lane >> 2, tig = lane & 3;

    for (int i = tid; i < 32 * 32; i += 256) {
        int r = i >> 5, f4 = i & 31;
        int n = a0 + r; if (n >= N) n = N - 1;
        cpa16(Xs + r * XSF + f4 * 4, g_embT + (size_t)n * 128 + f4 * 4);
    }
    for (int i = tid; i < 32 * 16; i += 256) {
        int r = i >> 4, c4 = i & 15;
        int n = a0 + r; if (n >= N) n = N - 1;
        cpa16(sa + r * 64 + c4 * 4, g_acc + (size_t)n * 64 + c4 * 4);
    }
    for (int i = tid; i < 16 * 32; i += 256) {
        cpa16(Wgfs + i * 4, Wgf + i * 4);
    }
    for (int i = tid; i < 16 * 128; i += 256) {
        int r = i >> 7, c4 = i & 127;
        cpa16(Wb0 + r * WSC + c4 * 4, g_aghT + (size_t)r * 512 + c4 * 4);
    }
    CP_COMMIT();
    for (int i = tid; i < 16 * 128; i += 256) {
        int r = i >> 7, c4 = i & 127;
        cpa16(Wb1 + r * WSC + c4 * 4, g_aghT + (size_t)(16 + r) * 512 + c4 * 4);
    }
    CP_COMMIT();

    float acc[2][8][4];
    #pragma unroll
    for (int mt = 0; mt < 2; mt++)
        #pragma unroll
        for (int nt = 0; nt < 8; nt++)
            #pragma unroll
            for (int e = 0; e < 4; e++) acc[mt][nt][e] = 0.f;

    for (int c = 0; c < 8; c++) {
        CP_WAIT1();
        __syncthreads();
        float* wb = (c & 1) ? Wb1 : Wb0;
        #pragma unroll
        for (int ks = 0; ks < 16; ks += 8) {
            int kg = c * 16 + ks;
            uint32_t A[2][4];
            #pragma unroll
            for (int mt = 0; mt < 2; mt++) {
                int row = 16 * mt + gid;
                A[mt][0] = fu(Xs[row * XSF + kg + tig]);
                A[mt][1] = fu(Xs[(row + 8) * XSF + kg + tig]);
                A[mt][2] = fu(Xs[row * XSF + kg + tig + 4]);
                A[mt][3] = fu(Xs[(row + 8) * XSF + kg + tig + 4]);
            }
            #pragma unroll
            for (int nt = 0; nt < 8; nt++) {
                int col = 64 * wn + 8 * nt + gid;
                uint32_t B[2];
                B[0] = fu(wb[(ks + tig) * WSC + col]);
                B[1] = fu(wb[(ks + tig + 4) * WSC + col]);
                mma_tf32(acc[0][nt], A[0], B);
                mma_tf32(acc[1][nt], A[1], B);
            }
        }
        __syncthreads();
        if (c + 2 < 8) {
            float* dst = (c & 1) ? Wb1 : Wb0;
            for (int i = tid; i < 16 * 128; i += 256) {
                int r = i >> 7, c4 = i & 127;
                cpa16(dst + r * WSC + c4 * 4,
                      g_aghT + (size_t)((c + 2) * 16 + r) * 512 + c4 * 4);
            }
        }
        CP_COMMIT();
    }

    #pragma unroll
    for (int mt = 0; mt < 2; mt++) {
        int r0 = 16 * mt + gid;
        #pragma unroll
        for (int nt = 0; nt < 8; nt++) {
            int col = 64 * wn + 8 * nt + 2 * tig;
            *reinterpret_cast<float2*>(&Ms[r0 * MSF + col]) =
                make_float2(acc[mt][nt][0], acc[mt][nt][1]);
            *reinterpret_cast<float2*>(&Ms[(r0 + 8) * MSF + col]) =
                make_float2(acc[mt][nt][2], acc[mt][nt][3]);
        }
    }
    __syncthreads();

    for (int idx = tid; idx < 32 * 128; idx += 256) {
        int r = idx >> 7, f = idx & 127;
        int n = a0 + r;
        if (n >= N) continue;
        float m = 0.f;
        #pragma unroll
        for (int g = 0; g < 16; g++) m += sa[r * 64 + g] * Wgfs[g * 128 + f];
        float* msg = g_msg + (size_t)n * 288;
        msg[f]       = f2tf(Xs[r * XSF + f] * m);
        msg[160 + f] = f2tf(q[n] * m);
    }
    for (int idx = tid; idx < 32 * 32; idx += 256) {
        int r = idx >> 5, h = idx & 31;
        int n = a0 + r;
        if (n >= N) continue;
        float v0 = 0.f, v1 = 0.f, v2 = 0.f;
        #pragma unroll
        for (int g = 0; g < 16; g++) {
            float Mv = Ms[r * MSF + g * 32 + h];
            v0 += sa[r * 64 + 16 + g] * Mv;
            v1 += sa[r * 64 + 32 + g] * Mv;
            v2 += sa[r * 64 + 48 + g] * Mv;
        }
        float sq = v0 * v0 + v1 * v1 + v2 * v2;
        g_msg[(size_t)n * 288 + 128 + h] = (sq > 0.f) ? f2tf(sqrtf(sq)) : 0.f;
    }
}

// ---------------------------------------------------------------------------
// Launch 4 (PROFILED): Layer 1 (288 -> 256, gelu). Resident weight half.
// grid (148, 2): blockIdx.y = column half. 256 threads, 8 warps (2m x 4n),
// 64-atom tiles looped with stride 148. smem 226816 B.
// ---------------------------------------------------------------------------
#define L1WS 132
#define L1XS 292
#define L1_OX (288 * L1WS)                  // 38016
#define L1_SMEM ((L1_OX + 64 * L1XS) * 4)   // 226816 B

__global__ void __launch_bounds__(256, 1) k_l1(const float* __restrict__ b1, int N) {
    extern __shared__ float sm[];
    float* W  = sm;
    float* Xs = sm + L1_OX;
    int tid = threadIdx.x;
    int lane = tid & 31, warp = tid >> 5;
    int gid = lane >> 2, tig = lane & 3;
    int wm = warp >> 2, wn = warp & 3;
    int half = blockIdx.y;

    // stage resident W1 half: 288 rows x 128 cols
    for (int i = tid; i < 288 * 32; i += 256) {
        int r = i >> 5, c4 = i & 31;
        cpa16(W + r * L1WS + c4 * 4, g_w1t + (size_t)r * 256 + half * 128 + c4 * 4);
    }
    CP_COMMIT();

    int tiles = (N + 63) >> 6;
    for (int t = blockIdx.x; t < tiles; t += gridDim.x) {
        int a0 = t * 64;
        __syncthreads();     // all warps done reading Xs from previous tile
        for (int i = tid; i < 64 * 72; i += 256) {
            int r = i / 72, k4 = i - r * 72;
            int n = a0 + r; if (n >= N) n = N - 1;
            cpa16(Xs + r * L1XS + k4 * 4, g_msg + (size_t)n * 288 + k4 * 4);
        }
        CP_COMMIT(); CP_WAIT0();
        __syncthreads();

        float acc[2][4][4];
        #pragma unroll
        for (int mt = 0; mt < 2; mt++)
            #pragma unroll
            for (int nt = 0; nt < 4; nt++)
                #pragma unroll
                for (int e = 0; e < 4; e++) acc[mt][nt][e] = 0.f;

        #pragma unroll 4
        for (int kg = 0; kg < 288; kg += 8) {
            uint32_t A[2][4];
            #pragma unroll
            for (int mt = 0; mt < 2; mt++) {
                int row = 32 * wm + 16 * mt + gid;
                A[mt][0] = fu(Xs[row * L1XS + kg + tig]);
                A[mt][1] = fu(Xs[(row + 8) * L1XS + kg + tig]);
                A[mt][2] = fu(Xs[row * L1XS + kg + tig + 4]);
                A[mt][3] = fu(Xs[(row + 8) * L1XS + kg + tig + 4]);
            }
            #pragma unroll
            for (int nt = 0; nt < 4; nt++) {
                int col = 32 * wn + 8 * nt + gid;
                uint32_t B[2];
                B[0] = fu(W[(kg + tig) * L1WS + col]);
                B[1] = fu(W[(kg + tig + 4) * L1WS + col]);
                mma_tf32(acc[0][nt], A[0], B);
                mma_tf32(acc[1][nt], A[1], B);
            }
        }

        // epilogue: gelu + bias, write tf32-rounded H1 to global
        #pragma unroll
        for (int mt = 0; mt < 2; mt++) {
            int row0 = 32 * wm + 16 * mt + gid;
            int n0 = a0 + row0, n1 = n0 + 8;
            #pragma unroll
            for (int nt = 0; nt < 4; nt++) {
                int col = 32 * wn + 8 * nt + 2 * tig;
                int j = half * 128 + col;
                float bb0 = b1[j], bb1 = b1[j + 1];
                if (n0 < N)
                    *reinterpret_cast<float2*>(&g_h1[(size_t)n0 * 256 + j]) =
                        make_float2(f2tf(gelu_exact(acc[mt][nt][0] + bb0)),
                                    f2tf(gelu_exact(acc[mt][nt][1] + bb1)));
                if (n1 < N)
                    *reinterpret_cast<float2*>(&g_h1[(size_t)n1 * 256 + j]) =
                        make_float2(f2tf(gelu_exact(acc[mt][nt][2] + bb0)),
                                    f2tf(gelu_exact(acc[mt][nt][3] + bb1)));
            }
        }
    }
}

// ---------------------------------------------------------------------------
// Launch 5: Layer 2 (256 -> 128, gelu). Full W2 resident. grid 148.
// smem 201728 B. Writes H2 into g_embT (reused, emb no longer needed).
// ---------------------------------------------------------------------------
#define L2WS 132
#define L2XS 260
#define L2_OX (256 * L2WS)                  // 33792
#define L2_SMEM ((L2_OX + 64 * L2XS) * 4)   // 201728 B

__global__ void __launch_bounds__(256, 1) k_l2(const float* __restrict__ b2, int N) {
    extern __shared__ float sm[];
    float* W  = sm;
    float* Xs = sm + L2_OX;
    int tid = threadIdx.x;
    int lane = tid & 31, warp = tid >> 5;
    int gid = lane >> 2, tig = lane & 3;
    int wm = warp >> 2, wn = warp & 3;

    for (int i = tid; i < 256 * 32; i += 256) {
        int r = i >> 5, c4 = i & 31;
        cpa16(W + r * L2WS + c4 * 4, g_w2t + (size_t)r * 128 + c4 * 4);
    }
    CP_COMMIT();

    int tiles = (N + 63) >> 6;
    for (int t = blockIdx.x; t < tiles; t += gridDim.x) {
        int a0 = t * 64;
        __syncthreads();
        for (int i = tid; i < 64 * 64; i += 256) {
            int r = i >> 6, c4 = i & 63;
            int n = a0 + r; if (n >= N) n = N - 1;
            cpa16(Xs + r * L2XS + c4 * 4, g_h1 + (size_t)n * 256 + c4 * 4);
        }
        CP_COMMIT(); CP_WAIT0();
        __syncthreads();

        float acc[2][4][4];
        #pragma unroll
        for (int mt = 0; mt < 2; mt++)
            #pragma unroll
            for (int nt = 0; nt < 4; nt++)
                #pragma unroll
                for (int e = 0; e < 4; e++) acc[mt][nt][e] = 0.f;

        #pragma unroll 4
        for (int kg = 0; kg < 256; kg += 8) {
            uint32_t A[2][4];
            #pragma unroll
            for (int mt = 0; mt < 2; mt++) {
                int row = 32 * wm + 16 * mt + gid;
                A[mt][0] = fu(Xs[row * L2XS + kg + tig]);
                A[mt][1] = fu(Xs[(row + 8) * L2XS + kg + tig]);
                A[mt][2] = fu(Xs[row * L2XS + kg + tig + 4]);
                A[mt][3] = fu(Xs[(row + 8) * L2XS + kg + tig + 4]);
            }
            #pragma unroll
            for (int nt = 0; nt < 4; nt++) {
                int col = 32 * wn + 8 * nt + gid;
                uint32_t B[2];
                B[0] = fu(W[(kg + tig) * L2WS + col]);
                B[1] = fu(W[(kg + tig + 4) * L2WS + col]);
                mma_tf32(acc[0][nt], A[0], B);
                mma_tf32(acc[1][nt], A[1], B);
            }
        }

        #pragma unroll
        for (int mt = 0; mt < 2; mt++) {
            int row0 = 32 * wm + 16 * mt + gid;
            int n0 = a0 + row0, n1 = n0 + 8;
            #pragma unroll
            for (int nt = 0; nt < 4; nt++) {
                int j = 32 * wn + 8 * nt + 2 * tig;
                float bb0 = b2[j], bb1 = b2[j + 1];
                if (n0 < N)
                    *reinterpret_cast<float2*>(&g_embT[(size_t)n0 * 128 + j]) =
                        make_float2(f2tf(gelu_exact(acc[mt][nt][0] + bb0)),
                                    f2tf(gelu_exact(acc[mt][nt][1] + bb1)));
                if (n1 < N)
                    *reinterpret_cast<float2*>(&g_embT[(size_t)n1 * 128 + j]) =
                        make_float2(f2tf(gelu_exact(acc[mt][nt][2] + bb0)),
                                    f2tf(gelu_exact(acc[mt][nt][3] + bb1)));
            }
        }
    }
}

// ---------------------------------------------------------------------------
// Launch 6: Layer 3 (128 -> 130, linear) + output scatter. W3 resident.
// grid 296 (2 CTAs/SM). smem 103424 B.
// ---------------------------------------------------------------------------
#define L3WS 136
#define L3XS 132
#define L3_OX (128 * L3WS)                  // 17408
#define L3_SMEM ((L3_OX + 64 * L3XS) * 4)   // 103424 B

__global__ void __launch_bounds__(256, 2) k_l3(const float* __restrict__ b3,
                                               float* __restrict__ out, int N) {
    extern __shared__ float sm[];
    float* W  = sm;
    float* Xs = sm + L3_OX;
    int tid = threadIdx.x;
    int lane = tid & 31, warp = tid >> 5;
    int gid = lane >> 2, tig = lane & 3;
    int wm = warp >> 2, wn = warp & 3;

    for (int i = tid; i < 128 * 34; i += 256) {
        int r = i / 34, c4 = i - r * 34;
        cpa16(W + r * L3WS + c4 * 4, g_w3t + (size_t)r * 136 + c4 * 4);
    }
    CP_COMMIT();

    size_t dq_off = (size_t)N * 128;
    size_t f_off = dq_off + (size_t)N;
    int tiles = (N + 63) >> 6;
    for (int t = blockIdx.x; t < tiles; t += gridDim.x) {
        int a0 = t * 64;
        __syncthreads();
        for (int i = tid; i < 64 * 32; i += 256) {
            int r = i >> 5, c4 = i & 31;
            int n = a0 + r; if (n >= N) n = N - 1;
            cpa16(Xs + r * L3XS + c4 * 4, g_embT + (size_t)n * 128 + c4 * 4);
        }
        CP_COMMIT(); CP_WAIT0();
        __syncthreads();

        // 17 n-tiles of 8 cols over 4 warp-columns: u = 5*wn + nt, valid u < 17
        float acc[2][5][4];
        #pragma unroll
        for (int mt = 0; mt < 2; mt++)
            #pragma unroll
            for (int nt = 0; nt < 5; nt++)
                #pragma unroll
                for (int e = 0; e < 4; e++) acc[mt][nt][e] = 0.f;

        #pragma unroll 4
        for (int kg = 0; kg < 128; kg += 8) {
            uint32_t A[2][4];
            #pragma unroll
            for (int mt = 0; mt < 2; mt++) {
                int row = 32 * wm + 16 * mt + gid;
                A[mt][0] = fu(Xs[row * L3XS + kg + tig]);
                A[mt][1] = fu(Xs[(row + 8) * L3XS + kg + tig]);
                A[mt][2] = fu(Xs[row * L3XS + kg + tig + 4]);
                A[mt][3] = fu(Xs[(row + 8) * L3XS + kg + tig + 4]);
            }
            #pragma unroll
            for (int nt = 0; nt < 5; nt++) {
                int u = 5 * wn + nt;
                if (u >= 17) break;
                int col = 8 * u + gid;
                uint32_t B[2];
                B[0] = fu(W[(kg + tig) * L3WS + col]);
                B[1] = fu(W[(kg + tig + 4) * L3WS + col]);
                mma_tf32(acc[0][nt], A[0], B);
                mma_tf32(acc[1][nt], A[1], B);
            }
        }

        #pragma unroll
        for (int mt = 0; mt < 2; mt++) {
            #pragma unroll
            for (int nt = 0; nt < 5; nt++) {
                int u = 5 * wn + nt;
                if (u >= 17) break;
                #pragma unroll
                for (int e = 0; e < 4; e++) {
                    int row = 32 * wm + 16 * mt + gid + ((e >> 1) ? 8 : 0);
                    int j = 8 * u + 2 * tig + (e & 1);
                    int n = a0 + row;
                    if (n >= N || j >= 130) continue;
                    float v = acc[mt][nt][e] + b3[j];
                    if (j == 0)      out[dq_off + n] = v;
                    else if (j == 1) out[f_off + n] = v;
                    else             out[(size_t)n * 128 + (j - 2)] = v;
                }
            }
        }
    }
}

// ---------------------------------------------------------------------------
extern "C" void kernel_launch(void* const* d_in, const int* in_sizes, int n_in,
                              void* d_out, int out_size) {
    const float* emb  = (const float*)d_in[0];
    const float* q    = (const float*)d_in[1];
    const int*   pidx = (const int*)d_in[2];
    const float* gs   = (const float*)d_in[3];
    const float* gv   = (const float*)d_in[4];
    const float* agh  = (const float*)d_in[5];
    const float* Wgf  = (const float*)d_in[6];
    const float* W1   = (const float*)d_in[7];
    const float* b1   = (const float*)d_in[8];
    const float* W2   = (const float*)d_in[9];
    const float* b2   = (const float*)d_in[10];
    const float* W3   = (const float*)d_in[11];
    const float* b3   = (const float*)d_in[12];
    float* out = (float*)d_out;

    int N = in_sizes[0] / 128;
    int P = in_sizes[2] / 2;
    if (N > NMAX) N = NMAX;
    const int* idxj = pidx + P;

    // 1: tf32 conversion + zero accumulators (merged)
    int cvt_tot = CVT_W + N * 32 + N * 16;
    k_cvt<<<(cvt_tot + 255) / 256, 256>>>(agh, W1, W2, W3, emb, N);

    // 2: pair scatter
    long long Q = (long long)P * 16;
    k_scatter<<<(int)((Q + 255) / 256), 256>>>(idxj, gs, gv, P);

    // 3: fused GEMM-M + assemble
    cudaFuncSetAttribute(k_gemm_assemble, cudaFuncAttributeMaxDynamicSharedMemorySize, GA_SMEM);
    k_gemm_assemble<<<(N + 31) / 32, 256, GA_SMEM>>>(q, Wgf, N);

    // 4 (profiled): layer 1, resident weights
    cudaFuncSetAttribute(k_l1, cudaFuncAttributeMaxDynamicSharedMemorySize, L1_SMEM);
    k_l1<<<dim3(148, 2), 256, L1_SMEM>>>(b1, N);

    // 5: layer 2
    cudaFuncSetAttribute(k_l2, cudaFuncAttributeMaxDynamicSharedMemorySize, L2_SMEM);
    k_l2<<<148, 256, L2_SMEM>>>(b2, N);

    // 6: layer 3 + output scatter
    cudaFuncSetAttribute(k_l3, cudaFuncAttributeMaxDynamicSharedMemorySize, L3_SMEM);
    k_l3<<<296, 256, L3_SMEM>>>(b3, out, N);
}

// round 11
// speedup vs baseline: 1.2189x; 1.2189x over previous
#include <cuda_runtime.h>
#include <cuda_fp16.h>
#include <math.h>
#include <stdint.h>

// N=50000, P=1.6M, F=128, G=16, H=32, HID1=256, HID2=128, IN=288 (vec_q==0 dropped)
#define NMAX 50000

__device__ float  g_acc[NMAX * 64];             // [n][0:16]=Gsum, [16:64]=GVsum(d,g)
__device__ __half g_msgh[(size_t)NMAX * 288];   // MLP input, fp16
__device__ __half g_h1h[(size_t)NMAX * 256];    // layer1 activations fp16
__device__ __half g_h2h[(size_t)NMAX * 128];    // layer2 activations fp16
__device__ float  g_embT[(size_t)NMAX * 128];   // emb tf32 (gemm_assemble input)
__device__ float  g_aghT[128 * 512];            // agh tf32 [K][N]
__device__ __half g_w1h[256 * 288];             // W1^T fp16 [n][k]
__device__ __half g_w2h[128 * 256];             // W2^T fp16 [n][k]
__device__ __half g_w3h[136 * 128];             // W3^T fp16 [n][k], n padded 130->136

__device__ __forceinline__ float gelu_exact(float x) {
    return 0.5f * x * (1.0f + erff(x * 0.70710678118654752f));
}
__device__ __forceinline__ float f2tf(float x) {
    uint32_t r;
    asm("cvt.rna.tf32.f32 %0, %1;" : "=r"(r) : "f"(x));
    return __uint_as_float(r);
}
__device__ __forceinline__ void mma_tf32(float d[4], const uint32_t a[4],
                                         const uint32_t b[2]) {
    asm volatile(
        "mma.sync.aligned.m16n8k8.row.col.f32.tf32.tf32.f32 "
        "{%0,%1,%2,%3}, {%4,%5,%6,%7}, {%8,%9}, {%0,%1,%2,%3};"
        : "+f"(d[0]), "+f"(d[1]), "+f"(d[2]), "+f"(d[3])
        : "r"(a[0]), "r"(a[1]), "r"(a[2]), "r"(a[3]), "r"(b[0]), "r"(b[1]));
}
// fp16 m16n8k16: A row-major 4 regs, B col-major 2 regs, fp32 accum
__device__ __forceinline__ void mma_f16(float d[4], const uint32_t a[4],
                                        const uint32_t b[2]) {
    asm volatile(
        "mma.sync.aligned.m16n8k16.row.col.f32.f16.f16.f32 "
        "{%0,%1,%2,%3}, {%4,%5,%6,%7}, {%8,%9}, {%0,%1,%2,%3};"
        : "+f"(d[0]), "+f"(d[1]), "+f"(d[2]), "+f"(d[3])
        : "r"(a[0]), "r"(a[1]), "r"(a[2]), "r"(a[3]), "r"(b[0]), "r"(b[1]));
}
__device__ __forceinline__ uint32_t fu(float x) { return __float_as_uint(x); }
__device__ __forceinline__ uint32_t h2u(const __half* p) {
    return *reinterpret_cast<const uint32_t*>(p);
}

__device__ __forceinline__ void cpa16(void* s, const void* g) {
    uint32_t sp = (uint32_t)__cvta_generic_to_shared(s);
    asm volatile("cp.async.cg.shared.global [%0], [%1], 16;" :: "r"(sp), "l"(g));
}
#define CP_COMMIT() asm volatile("cp.async.commit_group;" ::: "memory")
#define CP_WAIT1()  asm volatile("cp.async.wait_group 1;" ::: "memory")
#define CP_WAIT0()  asm volatile("cp.async.wait_group 0;" ::: "memory")

// ---------------------------------------------------------------------------
// Launch 1: conversions — aghT tf32, W1/W2/W3 transposed fp16, emb tf32,
// zero g_acc.
// ---------------------------------------------------------------------------
#define CVT_W (128 * 512 + 256 * 288 + 128 * 256 + 136 * 128)
__global__ void k_cvt(const float* __restrict__ agh, const float* __restrict__ W1,
                      const float* __restrict__ W2, const float* __restrict__ W3,
                      const float* __restrict__ emb, int N) {
    int i = blockIdx.x * blockDim.x + threadIdx.x;
    if (i < 128 * 512) { g_aghT[i] = f2tf(agh[i]); return; }
    i -= 128 * 512;
    if (i < 256 * 288) {                       // W1^T [n][k]
        int n = i / 288, k = i - n * 288;
        g_w1h[i] = __float2half(W1[(size_t)k * 256 + n]);
        return;
    }
    i -= 256 * 288;
    if (i < 128 * 256) {                       // W2^T [n][k]
        int n = i >> 8, k = i & 255;
        g_w2h[i] = __float2half(W2[(size_t)k * 128 + n]);
        return;
    }
    i -= 128 * 256;
    if (i < 136 * 128) {                       // W3^T [n][k], zero-pad n>=130
        int n = i >> 7, k = i & 127;
        g_w3h[i] = (n < 130) ? __float2half(W3[(size_t)k * 130 + n]) : __float2half(0.f);
        return;
    }
    i -= 136 * 128;
    if (i < N * 32) {
        float4 v = reinterpret_cast<const float4*>(emb)[i];
        reinterpret_cast<float4*>(g_embT)[i] =
            make_float4(f2tf(v.x), f2tf(v.y), f2tf(v.z), f2tf(v.w));
        return;
    }
    i -= N * 32;
    if (i < N * 16)
        reinterpret_cast<float4*>(g_acc)[i] = make_float4(0.f, 0.f, 0.f, 0.f);
}

// ---------------------------------------------------------------------------
// Launch 2: pair scatter (unchanged, ~96us near-floor)
// ---------------------------------------------------------------------------
__global__ void k_scatter(const int* __restrict__ idxj, const float* __restrict__ gs,
                          const float* __restrict__ gv, int P) {
    long long q = (long long)blockIdx.x * blockDim.x + threadIdx.x;
    long long total = (long long)P * 16;
    if (q >= total) return;
    int p = (int)(q >> 4);
    int c = (int)(q & 15);
    int n = idxj[p];
    float4 v;
    float* dst;
    if (c < 4) {
        v = *reinterpret_cast<const float4*>(gs + (size_t)p * 16 + c * 4);
        dst = g_acc + (size_t)n * 64 + c * 4;
    } else {
        v = *reinterpret_cast<const float4*>(gv + (size_t)p * 48 + (c - 4) * 4);
        dst = g_acc + (size_t)n * 64 + 16 + (c - 4) * 4;
    }
    asm volatile("red.global.add.v4.f32 [%0], {%1,%2,%3,%4};"
                 :: "l"(dst), "f"(v.x), "f"(v.y), "f"(v.z), "f"(v.w)
                 : "memory");
}

// ---------------------------------------------------------------------------
// Launch 3: fused GEMM-M + assemble (tf32, known-good 90us); msg now fp16.
// ---------------------------------------------------------------------------
#define XSF 132
#define WSC 520
#define MSF 516
#define OXS 0
#define OSA 4224
#define OWG 6272
#define OWB 8320
#define GA_SMEM (24960 * 4)

__global__ void __launch_bounds__(256, 2) k_gemm_assemble(
    const float* __restrict__ q, const float* __restrict__ Wgf, int N) {
    extern __shared__ float sm[];
    float* Xs   = sm + OXS;
    float* sa   = sm + OSA;
    float* Wgfs = sm + OWG;
    float* Wb0  = sm + OWB;
    float* Wb1  = sm + OWB + 8320;
    float* Ms   = sm + OWB;
    int a0 = blockIdx.x * 32;
    int tid = threadIdx.x;
    int lane = tid & 31, wn = tid >> 5;
    int gid = lane >> 2, tig = lane & 3;

    for (int i = tid; i < 32 * 32; i += 256) {
        int r = i >> 5, f4 = i & 31;
        int n = a0 + r; if (n >= N) n = N - 1;
        cpa16(Xs + r * XSF + f4 * 4, g_embT + (size_t)n * 128 + f4 * 4);
    }
    for (int i = tid; i < 32 * 16; i += 256) {
        int r = i >> 4, c4 = i & 15;
        int n = a0 + r; if (n >= N) n = N - 1;
        cpa16(sa + r * 64 + c4 * 4, g_acc + (size_t)n * 64 + c4 * 4);
    }
    for (int i = tid; i < 16 * 32; i += 256) {
        cpa16(Wgfs + i * 4, Wgf + i * 4);
    }
    for (int i = tid; i < 16 * 128; i += 256) {
        int r = i >> 7, c4 = i & 127;
        cpa16(Wb0 + r * WSC + c4 * 4, g_aghT + (size_t)r * 512 + c4 * 4);
    }
    CP_COMMIT();
    for (int i = tid; i < 16 * 128; i += 256) {
        int r = i >> 7, c4 = i & 127;
        cpa16(Wb1 + r * WSC + c4 * 4, g_aghT + (size_t)(16 + r) * 512 + c4 * 4);
    }
    CP_COMMIT();

    float acc[2][8][4];
    #pragma unroll
    for (int mt = 0; mt < 2; mt++)
        #pragma unroll
        for (int nt = 0; nt < 8; nt++)
            #pragma unroll
            for (int e = 0; e < 4; e++) acc[mt][nt][e] = 0.f;

    for (int c = 0; c < 8; c++) {
        CP_WAIT1();
        __syncthreads();
        float* wb = (c & 1) ? Wb1 : Wb0;
        #pragma unroll
        for (int ks = 0; ks < 16; ks += 8) {
            int kg = c * 16 + ks;
            uint32_t A[2][4];
            #pragma unroll
            for (int mt = 0; mt < 2; mt++) {
                int row = 16 * mt + gid;
                A[mt][0] = fu(Xs[row * XSF + kg + tig]);
                A[mt][1] = fu(Xs[(row + 8) * XSF + kg + tig]);
                A[mt][2] = fu(Xs[row * XSF + kg + tig + 4]);
                A[mt][3] = fu(Xs[(row + 8) * XSF + kg + tig + 4]);
            }
            #pragma unroll
            for (int nt = 0; nt < 8; nt++) {
                int col = 64 * wn + 8 * nt + gid;
                uint32_t B[2];
                B[0] = fu(wb[(ks + tig) * WSC + col]);
                B[1] = fu(wb[(ks + tig + 4) * WSC + col]);
                mma_tf32(acc[0][nt], A[0], B);
                mma_tf32(acc[1][nt], A[1], B);
            }
        }
        __syncthreads();
        if (c + 2 < 8) {
            float* dst = (c & 1) ? Wb1 : Wb0;
            for (int i = tid; i < 16 * 128; i += 256) {
                int r = i >> 7, c4 = i & 127;
                cpa16(dst + r * WSC + c4 * 4,
                      g_aghT + (size_t)((c + 2) * 16 + r) * 512 + c4 * 4);
            }
        }
        CP_COMMIT();
    }

    #pragma unroll
    for (int mt = 0; mt < 2; mt++) {
        int r0 = 16 * mt + gid;
        #pragma unroll
        for (int nt = 0; nt < 8; nt++) {
            int col = 64 * wn + 8 * nt + 2 * tig;
            *reinterpret_cast<float2*>(&Ms[r0 * MSF + col]) =
                make_float2(acc[mt][nt][0], acc[mt][nt][1]);
            *reinterpret_cast<float2*>(&Ms[(r0 + 8) * MSF + col]) =
                make_float2(acc[mt][nt][2], acc[mt][nt][3]);
        }
    }
    __syncthreads();

    for (int idx = tid; idx < 32 * 128; idx += 256) {
        int r = idx >> 7, f = idx & 127;
        int n = a0 + r;
        if (n >= N) continue;
        float m = 0.f;
        #pragma unroll
        for (int g = 0; g < 16; g++) m += sa[r * 64 + g] * Wgfs[g * 128 + f];
        __half* msg = g_msgh + (size_t)n * 288;
        msg[f]       = __float2half(Xs[r * XSF + f] * m);
        msg[160 + f] = __float2half(q[n] * m);
    }
    for (int idx = tid; idx < 32 * 32; idx += 256) {
        int r = idx >> 5, h = idx & 31;
        int n = a0 + r;
        if (n >= N) continue;
        float v0 = 0.f, v1 = 0.f, v2 = 0.f;
        #pragma unroll
        for (int g = 0; g < 16; g++) {
            float Mv = Ms[r * MSF + g * 32 + h];
            v0 += sa[r * 64 + 16 + g] * Mv;
            v1 += sa[r * 64 + 32 + g] * Mv;
            v2 += sa[r * 64 + 48 + g] * Mv;
        }
        float sq = v0 * v0 + v1 * v1 + v2 * v2;
        g_msgh[(size_t)n * 288 + 128 + h] = __float2half((sq > 0.f) ? sqrtf(sq) : 0.f);
    }
}

// ---------------------------------------------------------------------------
// Launch 4 (PROFILED): Layer 1 (288 -> 256, gelu), fp16 m16n8k16.
// Full W1^T resident (256 x 296 halves), 64-atom act tiles. grid 148.
// smem = (256*296 + 64*296) * 2 = 189440 B.
// ---------------------------------------------------------------------------
#define L1KP 296
#define L1_OX (256 * L1KP)
#define L1_SMEM ((L1_OX + 64 * L1KP) * 2)

__global__ void __launch_bounds__(256, 1) k_l1(const float* __restrict__ b1, int N) {
    extern __shared__ __half smh[];
    __half* W  = smh;
    __half* Xs = smh + L1_OX;
    int tid = threadIdx.x;
    int lane = tid & 31, warp = tid >> 5;
    int gid = lane >> 2, tig = lane & 3;
    int wm = warp >> 2, wn = warp & 3;

    // stage resident W1^T: 256 n-rows x 288 k (36 x 8-half chunks per row)
    for (int i = tid; i < 256 * 36; i += 256) {
        int r = i / 36, u = i - r * 36;
        cpa16(W + r * L1KP + u * 8, g_w1h + (size_t)r * 288 + u * 8);
    }
    CP_COMMIT();

    int tiles = (N + 63) >> 6;
    for (int t = blockIdx.x; t < tiles; t += gridDim.x) {
        int a0 = t * 64;
        __syncthreads();
        for (int i = tid; i < 64 * 36; i += 256) {
            int r = i / 36, u = i - r * 36;
            int n = a0 + r; if (n >= N) n = N - 1;
            cpa16(Xs + r * L1KP + u * 8, g_msgh + (size_t)n * 288 + u * 8);
        }
        CP_COMMIT(); CP_WAIT0();
        __syncthreads();

        float acc[2][8][4];
        #pragma unroll
        for (int mt = 0; mt < 2; mt++)
            #pragma unroll
            for (int nt = 0; nt < 8; nt++)
                #pragma unroll
                for (int e = 0; e < 4; e++) acc[mt][nt][e] = 0.f;

        #pragma unroll 2
        for (int kg = 0; kg < 288; kg += 16) {
            uint32_t A[2][4];
            #pragma unroll
            for (int mt = 0; mt < 2; mt++) {
                int row = 32 * wm + 16 * mt + gid;
                A[mt][0] = h2u(&Xs[row * L1KP + kg + tig * 2]);
                A[mt][1] = h2u(&Xs[(row + 8) * L1KP + kg + tig * 2]);
                A[mt][2] = h2u(&Xs[row * L1KP + kg + tig * 2 + 8]);
                A[mt][3] = h2u(&Xs[(row + 8) * L1KP + kg + tig * 2 + 8]);
            }
            #pragma unroll
            for (int nt = 0; nt < 8; nt++) {
                int nn = 64 * wn + 8 * nt + gid;
                uint32_t B[2];
                B[0] = h2u(&W[nn * L1KP + kg + tig * 2]);
                B[1] = h2u(&W[nn * L1KP + kg + tig * 2 + 8]);
                mma_f16(acc[0][nt], A[0], B);
                mma_f16(acc[1][nt], A[1], B);
            }
        }

        #pragma unroll
        for (int mt = 0; mt < 2; mt++) {
            int row0 = 32 * wm + 16 * mt + gid;
            int n0 = a0 + row0, n1 = n0 + 8;
            #pragma unroll
            for (int nt = 0; nt < 8; nt++) {
                int col = 64 * wn + 8 * nt + 2 * tig;
                float bb0 = b1[col], bb1 = b1[col + 1];
                if (n0 < N)
                    *reinterpret_cast<__half2*>(&g_h1h[(size_t)n0 * 256 + col]) =
                        __floats2half2_rn(gelu_exact(acc[mt][nt][0] + bb0),
                                          gelu_exact(acc[mt][nt][1] + bb1));
                if (n1 < N)
                    *reinterpret_cast<__half2*>(&g_h1h[(size_t)n1 * 256 + col]) =
                        __floats2half2_rn(gelu_exact(acc[mt][nt][2] + bb0),
                                          gelu_exact(acc[mt][nt][3] + bb1));
            }
        }
    }
}

// ---------------------------------------------------------------------------
// Launch 5: Layer 2 (256 -> 128, gelu), fp16. Full W2^T resident.
// smem = (128*264 + 64*264) * 2 = 101376 B. grid 296 (2 CTAs/SM).
// ---------------------------------------------------------------------------
#define L2KP 264
#define L2_OX (128 * L2KP)
#define L2_SMEM ((L2_OX + 64 * L2KP) * 2)

__global__ void __launch_bounds__(256, 2) k_l2(const float* __restrict__ b2, int N) {
    extern __shared__ __half smh[];
    __half* W  = smh;
    __half* Xs = smh + L2_OX;
    int tid = threadIdx.x;
    int lane = tid & 31, warp = tid >> 5;
    int gid = lane >> 2, tig = lane & 3;
    int wm = warp >> 2, wn = warp & 3;

    for (int i = tid; i < 128 * 32; i += 256) {
        int r = i >> 5, u = i & 31;
        cpa16(W + r * L2KP + u * 8, g_w2h + (size_t)r * 256 + u * 8);
    }
    CP_COMMIT();

    int tiles = (N + 63) >> 6;
    for (int t = blockIdx.x; t < tiles; t += gridDim.x) {
        int a0 = t * 64;
        __syncthreads();
        for (int i = tid; i < 64 * 32; i += 256) {
            int r = i >> 5, u = i & 31;
            int n = a0 + r; if (n >= N) n = N - 1;
            cpa16(Xs + r * L2KP + u * 8, g_h1h + (size_t)n * 256 + u * 8);
        }
        CP_COMMIT(); CP_WAIT0();
        __syncthreads();

        float acc[2][4][4];
        #pragma unroll
        for (int mt = 0; mt < 2; mt++)
            #pragma unroll
            for (int nt = 0; nt < 4; nt++)
                #pragma unroll
                for (int e = 0; e < 4; e++) acc[mt][nt][e] = 0.f;

        #pragma unroll 2
        for (int kg = 0; kg < 256; kg += 16) {
            uint32_t A[2][4];
            #pragma unroll
            for (int mt = 0; mt < 2; mt++) {
                int row = 32 * wm + 16 * mt + gid;
                A[mt][0] = h2u(&Xs[row * L2KP + kg + tig * 2]);
                A[mt][1] = h2u(&Xs[(row + 8) * L2KP + kg + tig * 2]);
                A[mt][2] = h2u(&Xs[row * L2KP + kg + tig * 2 + 8]);
                A[mt][3] = h2u(&Xs[(row + 8) * L2KP + kg + tig * 2 + 8]);
            }
            #pragma unroll
            for (int nt = 0; nt < 4; nt++) {
                int nn = 32 * wn + 8 * nt + gid;
                uint32_t B[2];
                B[0] = h2u(&W[nn * L2KP + kg + tig * 2]);
                B[1] = h2u(&W[nn * L2KP + kg + tig * 2 + 8]);
                mma_f16(acc[0][nt], A[0], B);
                mma_f16(acc[1][nt], A[1], B);
            }
        }

        #pragma unroll
        for (int mt = 0; mt < 2; mt++) {
            int row0 = 32 * wm + 16 * mt + gid;
            int n0 = a0 + row0, n1 = n0 + 8;
            #pragma unroll
            for (int nt = 0; nt < 4; nt++) {
                int col = 32 * wn + 8 * nt + 2 * tig;
                float bb0 = b2[col], bb1 = b2[col + 1];
                if (n0 < N)
                    *reinterpret_cast<__half2*>(&g_h2h[(size_t)n0 * 128 + col]) =
                        __floats2half2_rn(gelu_exact(acc[mt][nt][0] + bb0),
                                          gelu_exact(acc[mt][nt][1] + bb1));
                if (n1 < N)
                    *reinterpret_cast<__half2*>(&g_h2h[(size_t)n1 * 128 + col]) =
                        __floats2half2_rn(gelu_exact(acc[mt][nt][2] + bb0),
                                          gelu_exact(acc[mt][nt][3] + bb1));
            }
        }
    }
}

// ---------------------------------------------------------------------------
// Launch 6: Layer 3 (128 -> 130, linear) + output scatter, fp16.
// W3^T resident (136 x 136 halves). smem = (136*136 + 64*136)*2 = 54400 B.
// grid 296 (2 CTAs/SM).
// ---------------------------------------------------------------------------
#define L3KP 136
#define L3_OX (136 * L3KP)
#define L3_SMEM ((L3_OX + 64 * L3KP) * 2)

__global__ void __launch_bounds__(256, 2) k_l3(const float* __restrict__ b3,
                                               float* __restrict__ out, int N) {
    extern __shared__ __half smh[];
    __half* W  = smh;
    __half* Xs = smh + L3_OX;
    int tid = threadIdx.x;
    int lane = tid & 31, warp = tid >> 5;
    int gid = lane >> 2, tig = lane & 3;
    int wm = warp >> 2, wn = warp & 3;

    for (int i = tid; i < 136 * 16; i += 256) {
        int r = i >> 4, u = i & 15;
        cpa16(W + r * L3KP + u * 8, g_w3h + (size_t)r * 128 + u * 8);
    }
    CP_COMMIT();

    size_t dq_off = (size_t)N * 128;
    size_t f_off = dq_off + (size_t)N;
    int tiles = (N + 63) >> 6;
    for (int t = blockIdx.x; t < tiles; t += gridDim.x) {
        int a0 = t * 64;
        __syncthreads();
        for (int i = tid; i < 64 * 16; i += 256) {
            int r = i >> 4, u = i & 15;
            int n = a0 + r; if (n >= N) n = N - 1;
            cpa16(Xs + r * L3KP + u * 8, g_h2h + (size_t)n * 128 + u * 8);
        }
        CP_COMMIT(); CP_WAIT0();
        __syncthreads();

        // 17 n-tiles over 4 warp-columns: u = 5*wn + nt (u < 17)
        float acc[2][5][4];
        #pragma unroll
        for (int mt = 0; mt < 2; mt++)
            #pragma unroll
            for (int nt = 0; nt < 5; nt++)
                #pragma unroll
                for (int e = 0; e < 4; e++) acc[mt][nt][e] = 0.f;

        #pragma unroll
        for (int kg = 0; kg < 128; kg += 16) {
            uint32_t A[2][4];
            #pragma unroll
            for (int mt = 0; mt < 2; mt++) {
                int row = 32 * wm + 16 * mt + gid;
                A[mt][0] = h2u(&Xs[row * L3KP + kg + tig * 2]);
                A[mt][1] = h2u(&Xs[(row + 8) * L3KP + kg + tig * 2]);
                A[mt][2] = h2u(&Xs[row * L3KP + kg + tig * 2 + 8]);
                A[mt][3] = h2u(&Xs[(row + 8) * L3KP + kg + tig * 2 + 8]);
            }
            #pragma unroll
            for (int nt = 0; nt < 5; nt++) {
                int u = 5 * wn + nt;
                if (u >= 17) break;
                int nn = 8 * u + gid;
                uint32_t B[2];
                B[0] = h2u(&W[nn * L3KP + kg + tig * 2]);
                B[1] = h2u(&W[nn * L3KP + kg + tig * 2 + 8]);
                mma_f16(acc[0][nt], A[0], B);
                mma_f16(acc[1][nt], A[1], B);
            }
        }

        #pragma unroll
        for (int mt = 0; mt < 2; mt++) {
            #pragma unroll
            for (int nt = 0; nt < 5; nt++) {
                int u = 5 * wn + nt;
                if (u >= 17) break;
                #pragma unroll
                for (int e = 0; e < 4; e++) {
                    int row = 32 * wm + 16 * mt + gid + ((e >> 1) ? 8 : 0);
                    int j = 8 * u + 2 * tig + (e & 1);
                    int n = a0 + row;
                    if (n >= N || j >= 130) continue;
                    float v = acc[mt][nt][e] + b3[j];
                    if (j == 0)      out[dq_off + n] = v;
                    else if (j == 1) out[f_off + n] = v;
                    else             out[(size_t)n * 128 + (j - 2)] = v;
                }
            }
        }
    }
}

// ---------------------------------------------------------------------------
extern "C" void kernel_launch(void* const* d_in, const int* in_sizes, int n_in,
                              void* d_out, int out_size) {
    const float* emb  = (const float*)d_in[0];
    const float* q    = (const float*)d_in[1];
    const int*   pidx = (const int*)d_in[2];
    const float* gs   = (const float*)d_in[3];
    const float* gv   = (const float*)d_in[4];
    const float* agh  = (const float*)d_in[5];
    const float* Wgf  = (const float*)d_in[6];
    const float* W1   = (const float*)d_in[7];
    const float* b1   = (const float*)d_in[8];
    const float* W2   = (const float*)d_in[9];
    const float* b2   = (const float*)d_in[10];
    const float* W3   = (const float*)d_in[11];
    const float* b3   = (const float*)d_in[12];
    float* out = (float*)d_out;

    int N = in_sizes[0] / 128;
    int P = in_sizes[2] / 2;
    if (N > NMAX) N = NMAX;
    const int* idxj = pidx + P;

    // 1: conversions + zero accumulators
    int cvt_tot = CVT_W + N * 32 + N * 16;
    k_cvt<<<(cvt_tot + 255) / 256, 256>>>(agh, W1, W2, W3, emb, N);

    // 2: pair scatter
    long long Q = (long long)P * 16;
    k_scatter<<<(int)((Q + 255) / 256), 256>>>(idxj, gs, gv, P);

    // 3: fused GEMM-M + assemble (tf32)
    cudaFuncSetAttribute(k_gemm_assemble, cudaFuncAttributeMaxDynamicSharedMemorySize, GA_SMEM);
    k_gemm_assemble<<<(N + 31) / 32, 256, GA_SMEM>>>(q, Wgf, N);

    // 4 (profiled): layer 1 fp16
    cudaFuncSetAttribute(k_l1, cudaFuncAttributeMaxDynamicSharedMemorySize, L1_SMEM);
    k_l1<<<148, 256, L1_SMEM>>>(b1, N);

    // 5: layer 2 fp16
    cudaFuncSetAttribute(k_l2, cudaFuncAttributeMaxDynamicSharedMemorySize, L2_SMEM);
    k_l2<<<296, 256, L2_SMEM>>>(b2, N);

    // 6: layer 3 fp16 + output scatter
    cudaFuncSetAttribute(k_l3, cudaFuncAttributeMaxDynamicSharedMemorySize, L3_SMEM);
    k_l3<<<296, 256, L3_SMEM>>>(b3, out, N);
}

// round 12
// speedup vs baseline: 1.2229x; 1.0033x over previous
#include <cuda_runtime.h>
#include <cuda_fp16.h>
#include <math.h>
#include <stdint.h>

// N=50000, P=1.6M, F=128, G=16, H=32, HID1=256, HID2=128, IN=288 (vec_q==0 dropped)
#define NMAX 50000

__device__ float  g_acc[NMAX * 64];             // [n][0:16]=Gsum, [16:64]=GVsum(d,g)
__device__ __half g_msgh[(size_t)NMAX * 288];   // MLP input fp16
__device__ __half g_h1h[(size_t)NMAX * 256];    // layer1 activations fp16
__device__ __half g_h2h[(size_t)NMAX * 128];    // layer2 activations fp16
__device__ __half g_embh[(size_t)NMAX * 128];   // emb fp16
__device__ __half g_aghh[512 * 128];            // agh^T fp16 [n=512][k=128]
__device__ __half g_w1h[256 * 288];             // W1^T fp16 [n][k]
__device__ __half g_w2h[128 * 256];             // W2^T fp16 [n][k]
__device__ __half g_w3h[136 * 128];             // W3^T fp16 [n][k], n padded

__device__ __forceinline__ float gelu_exact(float x) {
    return 0.5f * x * (1.0f + erff(x * 0.70710678118654752f));
}
// fp16 m16n8k16: A row-major 4 regs, B col-major 2 regs, fp32 accum
__device__ __forceinline__ void mma_f16(float d[4], const uint32_t a[4],
                                        const uint32_t b[2]) {
    asm volatile(
        "mma.sync.aligned.m16n8k16.row.col.f32.f16.f16.f32 "
        "{%0,%1,%2,%3}, {%4,%5,%6,%7}, {%8,%9}, {%0,%1,%2,%3};"
        : "+f"(d[0]), "+f"(d[1]), "+f"(d[2]), "+f"(d[3])
        : "r"(a[0]), "r"(a[1]), "r"(a[2]), "r"(a[3]), "r"(b[0]), "r"(b[1]));
}
__device__ __forceinline__ uint32_t h2u(const __half* p) {
    return *reinterpret_cast<const uint32_t*>(p);
}
__device__ __forceinline__ void cpa16(void* s, const void* g) {
    uint32_t sp = (uint32_t)__cvta_generic_to_shared(s);
    asm volatile("cp.async.cg.shared.global [%0], [%1], 16;" :: "r"(sp), "l"(g));
}
#define CP_COMMIT() asm volatile("cp.async.commit_group;" ::: "memory")
#define CP_WAIT1()  asm volatile("cp.async.wait_group 1;" ::: "memory")
#define CP_WAIT0()  asm volatile("cp.async.wait_group 0;" ::: "memory")

// ---------------------------------------------------------------------------
// Launch 1: conversions — agh^T fp16, W1/W2/W3^T fp16, emb fp16, zero g_acc.
// ---------------------------------------------------------------------------
#define CVT_W (512 * 128 + 256 * 288 + 128 * 256 + 136 * 128)
__global__ void k_cvt(const float* __restrict__ agh, const float* __restrict__ W1,
                      const float* __restrict__ W2, const float* __restrict__ W3,
                      const float* __restrict__ emb, int N) {
    int i = blockIdx.x * blockDim.x + threadIdx.x;
    if (i < 512 * 128) {                        // agh^T [n=512][k=128]
        int n = i >> 7, k = i & 127;
        g_aghh[i] = __float2half(agh[(size_t)k * 512 + n]);
        return;
    }
    i -= 512 * 128;
    if (i < 256 * 288) {                        // W1^T [n][k]
        int n = i / 288, k = i - n * 288;
        g_w1h[i] = __float2half(W1[(size_t)k * 256 + n]);
        return;
    }
    i -= 256 * 288;
    if (i < 128 * 256) {                        // W2^T [n][k]
        int n = i >> 8, k = i & 255;
        g_w2h[i] = __float2half(W2[(size_t)k * 128 + n]);
        return;
    }
    i -= 128 * 256;
    if (i < 136 * 128) {                        // W3^T [n][k]
        int n = i >> 7, k = i & 127;
        g_w3h[i] = (n < 130) ? __float2half(W3[(size_t)k * 130 + n]) : __float2half(0.f);
        return;
    }
    i -= 136 * 128;
    if (i < N * 128) { g_embh[i] = __float2half(emb[i]); return; }
    i -= N * 128;
    if (i < N * 16)
        reinterpret_cast<float4*>(g_acc)[i] = make_float4(0.f, 0.f, 0.f, 0.f);
}

// ---------------------------------------------------------------------------
// Launch 2: pair scatter (unchanged, ~96us near-floor)
// ---------------------------------------------------------------------------
__global__ void k_scatter(const int* __restrict__ idxj, const float* __restrict__ gs,
                          const float* __restrict__ gv, int P) {
    long long q = (long long)blockIdx.x * blockDim.x + threadIdx.x;
    long long total = (long long)P * 16;
    if (q >= total) return;
    int p = (int)(q >> 4);
    int c = (int)(q & 15);
    int n = idxj[p];
    float4 v;
    float* dst;
    if (c < 4) {
        v = *reinterpret_cast<const float4*>(gs + (size_t)p * 16 + c * 4);
        dst = g_acc + (size_t)n * 64 + c * 4;
    } else {
        v = *reinterpret_cast<const float4*>(gv + (size_t)p * 48 + (c - 4) * 4);
        dst = g_acc + (size_t)n * 64 + 16 + (c - 4) * 4;
    }
    asm volatile("red.global.add.v4.f32 [%0], {%1,%2,%3,%4};"
                 :: "l"(dst), "f"(v.x), "f"(v.y), "f"(v.z), "f"(v.w)
                 : "memory");
}

// ---------------------------------------------------------------------------
// Launch 3: fused GEMM-M + assemble, fp16 m16n8k16.
// 32 atoms/CTA, agh^T staged in 4 k-chunks of 32 (double-buffered cp.async),
// Ms (fp32) overlays dead weight buffers post-MMA. smem 107008 B, 2 CTAs/SM.
// ---------------------------------------------------------------------------
#define GXP 136                 // Xsh stride (halves): 128 + 8
#define GBP 40                  // weight-chunk stride (halves): 32 + 8
#define MSF 516                 // Ms stride (floats)
#define GA_XS_B 0               // Xsh: 32*136*2 = 8704
#define GA_SA_B 8704            // sa fp32: 8192
#define GA_WG_B 16896           // Wgf fp32: 8192
#define GA_WB_B 25088           // Wb0: 512*40*2 = 40960
#define GA_WB1_B 66048          // Wb1: 40960 -> ends 107008
#define GA_SMEM 107008

__global__ void __launch_bounds__(256, 2) k_gemm_assemble(
    const float* __restrict__ q, const float* __restrict__ Wgf, int N) {
    extern __shared__ char smraw[];
    __half* Xsh  = reinterpret_cast<__half*>(smraw + GA_XS_B);
    float*  sa   = reinterpret_cast<float*>(smraw + GA_SA_B);
    float*  Wgfs = reinterpret_cast<float*>(smraw + GA_WG_B);
    __half* Wb0  = reinterpret_cast<__half*>(smraw + GA_WB_B);
    __half* Wb1  = reinterpret_cast<__half*>(smraw + GA_WB1_B);
    float*  Ms   = reinterpret_cast<float*>(smraw + GA_WB_B);   // overlay
    int a0 = blockIdx.x * 32;
    int tid = threadIdx.x;
    int lane = tid & 31, wn = tid >> 5;    // 8 warps x 64 cols
    int gid = lane >> 2, tig = lane & 3;

    // stage Xs (emb fp16): 32 rows x 16 cpa16
    for (int i = tid; i < 32 * 16; i += 256) {
        int r = i >> 4, u = i & 15;
        int n = a0 + r; if (n >= N) n = N - 1;
        cpa16(Xsh + r * GXP + u * 8, g_embh + (size_t)n * 128 + u * 8);
    }
    // sa (fp32)
    for (int i = tid; i < 32 * 16; i += 256) {
        int r = i >> 4, c4 = i & 15;
        int n = a0 + r; if (n >= N) n = N - 1;
        cpa16(sa + r * 64 + c4 * 4, g_acc + (size_t)n * 64 + c4 * 4);
    }
    // Wgf (fp32)
    for (int i = tid; i < 16 * 32; i += 256) {
        cpa16(Wgfs + i * 4, Wgf + i * 4);
    }
    // weight chunk 0: 512 n-rows x 32 k halves (4 cpa16/row)
    for (int i = tid; i < 512 * 4; i += 256) {
        int r = i >> 2, u = i & 3;
        cpa16(Wb0 + r * GBP + u * 8, g_aghh + (size_t)r * 128 + u * 8);
    }
    CP_COMMIT();
    for (int i = tid; i < 512 * 4; i += 256) {
        int r = i >> 2, u = i & 3;
        cpa16(Wb1 + r * GBP + u * 8, g_aghh + (size_t)r * 128 + 32 + u * 8);
    }
    CP_COMMIT();

    float acc[2][8][4];
    #pragma unroll
    for (int mt = 0; mt < 2; mt++)
        #pragma unroll
        for (int nt = 0; nt < 8; nt++)
            #pragma unroll
            for (int e = 0; e < 4; e++) acc[mt][nt][e] = 0.f;

    for (int c = 0; c < 4; c++) {
        CP_WAIT1();
        __syncthreads();
        __half* wb = (c & 1) ? Wb1 : Wb0;
        #pragma unroll
        for (int ks = 0; ks < 32; ks += 16) {
            int kg = c * 32 + ks;
            uint32_t A[2][4];
            #pragma unroll
            for (int mt = 0; mt < 2; mt++) {
                int row = 16 * mt + gid;
                A[mt][0] = h2u(&Xsh[row * GXP + kg + tig * 2]);
                A[mt][1] = h2u(&Xsh[(row + 8) * GXP + kg + tig * 2]);
                A[mt][2] = h2u(&Xsh[row * GXP + kg + tig * 2 + 8]);
                A[mt][3] = h2u(&Xsh[(row + 8) * GXP + kg + tig * 2 + 8]);
            }
            #pragma unroll
            for (int nt = 0; nt < 8; nt++) {
                int nn = 64 * wn + 8 * nt + gid;
                uint32_t B[2];
                B[0] = h2u(&wb[nn * GBP + ks + tig * 2]);
                B[1] = h2u(&wb[nn * GBP + ks + tig * 2 + 8]);
                mma_f16(acc[0][nt], A[0], B);
                mma_f16(acc[1][nt], A[1], B);
            }
        }
        __syncthreads();
        if (c + 2 < 4) {
            __half* dst = (c & 1) ? Wb1 : Wb0;
            for (int i = tid; i < 512 * 4; i += 256) {
                int r = i >> 2, u = i & 3;
                cpa16(dst + r * GBP + u * 8,
                      g_aghh + (size_t)r * 128 + (c + 2) * 32 + u * 8);
            }
        }
        CP_COMMIT();
    }

    // epilogue: store acc -> Ms (fp32, overlays dead weight buffers)
    #pragma unroll
    for (int mt = 0; mt < 2; mt++) {
        int r0 = 16 * mt + gid;
        #pragma unroll
        for (int nt = 0; nt < 8; nt++) {
            int col = 64 * wn + 8 * nt + 2 * tig;
            *reinterpret_cast<float2*>(&Ms[r0 * MSF + col]) =
                make_float2(acc[mt][nt][0], acc[mt][nt][1]);
            *reinterpret_cast<float2*>(&Ms[(r0 + 8) * MSF + col]) =
                make_float2(acc[mt][nt][2], acc[mt][nt][3]);
        }
    }
    __syncthreads();

    // mapped = Gsum . W_gf[:,f]; rad_emb = emb*mapped; rad_q = q*mapped
    for (int idx = tid; idx < 32 * 128; idx += 256) {
        int r = idx >> 7, f = idx & 127;
        int n = a0 + r;
        if (n >= N) continue;
        float m = 0.f;
        #pragma unroll
        for (int g = 0; g < 16; g++) m += sa[r * 64 + g] * Wgfs[g * 128 + f];
        __half* msg = g_msgh + (size_t)n * 288;
        msg[f]       = __float2half(__half2float(Xsh[r * GXP + f]) * m);
        msg[160 + f] = __float2half(q[n] * m);
    }
    // vec_emb[h] = safe_norm over d of sum_g GVsum[d,g]*M[g*32+h]
    for (int idx = tid; idx < 32 * 32; idx += 256) {
        int r = idx >> 5, h = idx & 31;
        int n = a0 + r;
        if (n >= N) continue;
        float v0 = 0.f, v1 = 0.f, v2 = 0.f;
        #pragma unroll
        for (int g = 0; g < 16; g++) {
            float Mv = Ms[r * MSF + g * 32 + h];
            v0 += sa[r * 64 + 16 + g] * Mv;
            v1 += sa[r * 64 + 32 + g] * Mv;
            v2 += sa[r * 64 + 48 + g] * Mv;
        }
        float sq = v0 * v0 + v1 * v1 + v2 * v2;
        g_msgh[(size_t)n * 288 + 128 + h] = __float2half((sq > 0.f) ? sqrtf(sq) : 0.f);
    }
}

// ---------------------------------------------------------------------------
// Launch 4 (PROFILED): Layer 1 (288 -> 256, gelu), fp16. (unchanged from R11)
// ---------------------------------------------------------------------------
#define L1KP 296
#define L1_OX (256 * L1KP)
#define L1_SMEM ((L1_OX + 64 * L1KP) * 2)

__global__ void __launch_bounds__(256, 1) k_l1(const float* __restrict__ b1, int N) {
    extern __shared__ __half smh[];
    __half* W  = smh;
    __half* Xs = smh + L1_OX;
    int tid = threadIdx.x;
    int lane = tid & 31, warp = tid >> 5;
    int gid = lane >> 2, tig = lane & 3;
    int wm = warp >> 2, wn = warp & 3;

    for (int i = tid; i < 256 * 36; i += 256) {
        int r = i / 36, u = i - r * 36;
        cpa16(W + r * L1KP + u * 8, g_w1h + (size_t)r * 288 + u * 8);
    }
    CP_COMMIT();

    int tiles = (N + 63) >> 6;
    for (int t = blockIdx.x; t < tiles; t += gridDim.x) {
        int a0 = t * 64;
        __syncthreads();
        for (int i = tid; i < 64 * 36; i += 256) {
            int r = i / 36, u = i - r * 36;
            int n = a0 + r; if (n >= N) n = N - 1;
            cpa16(Xs + r * L1KP + u * 8, g_msgh + (size_t)n * 288 + u * 8);
        }
        CP_COMMIT(); CP_WAIT0();
        __syncthreads();

        float acc[2][8][4];
        #pragma unroll
        for (int mt = 0; mt < 2; mt++)
            #pragma unroll
            for (int nt = 0; nt < 8; nt++)
                #pragma unroll
                for (int e = 0; e < 4; e++) acc[mt][nt][e] = 0.f;

        #pragma unroll 2
        for (int kg = 0; kg < 288; kg += 16) {
            uint32_t A[2][4];
            #pragma unroll
            for (int mt = 0; mt < 2; mt++) {
                int row = 32 * wm + 16 * mt + gid;
                A[mt][0] = h2u(&Xs[row * L1KP + kg + tig * 2]);
                A[mt][1] = h2u(&Xs[(row + 8) * L1KP + kg + tig * 2]);
                A[mt][2] = h2u(&Xs[row * L1KP + kg + tig * 2 + 8]);
                A[mt][3] = h2u(&Xs[(row + 8) * L1KP + kg + tig * 2 + 8]);
            }
            #pragma unroll
            for (int nt = 0; nt < 8; nt++) {
                int nn = 64 * wn + 8 * nt + gid;
                uint32_t B[2];
                B[0] = h2u(&W[nn * L1KP + kg + tig * 2]);
                B[1] = h2u(&W[nn * L1KP + kg + tig * 2 + 8]);
                mma_f16(acc[0][nt], A[0], B);
                mma_f16(acc[1][nt], A[1], B);
            }
        }

        #pragma unroll
        for (int mt = 0; mt < 2; mt++) {
            int row0 = 32 * wm + 16 * mt + gid;
            int n0 = a0 + row0, n1 = n0 + 8;
            #pragma unroll
            for (int nt = 0; nt < 8; nt++) {
                int col = 64 * wn + 8 * nt + 2 * tig;
                float bb0 = b1[col], bb1 = b1[col + 1];
                if (n0 < N)
                    *reinterpret_cast<__half2*>(&g_h1h[(size_t)n0 * 256 + col]) =
                        __floats2half2_rn(gelu_exact(acc[mt][nt][0] + bb0),
                                          gelu_exact(acc[mt][nt][1] + bb1));
                if (n1 < N)
                    *reinterpret_cast<__half2*>(&g_h1h[(size_t)n1 * 256 + col]) =
                        __floats2half2_rn(gelu_exact(acc[mt][nt][2] + bb0),
                                          gelu_exact(acc[mt][nt][3] + bb1));
            }
        }
    }
}

// ---------------------------------------------------------------------------
// Launch 5: Layer 2 (256 -> 128, gelu), fp16. (unchanged from R11)
// ---------------------------------------------------------------------------
#define L2KP 264
#define L2_OX (128 * L2KP)
#define L2_SMEM ((L2_OX + 64 * L2KP) * 2)

__global__ void __launch_bounds__(256, 2) k_l2(const float* __restrict__ b2, int N) {
    extern __shared__ __half smh[];
    __half* W  = smh;
    __half* Xs = smh + L2_OX;
    int tid = threadIdx.x;
    int lane = tid & 31, warp = tid >> 5;
    int gid = lane >> 2, tig = lane & 3;
    int wm = warp >> 2, wn = warp & 3;

    for (int i = tid; i < 128 * 32; i += 256) {
        int r = i >> 5, u = i & 31;
        cpa16(W + r * L2KP + u * 8, g_w2h + (size_t)r * 256 + u * 8);
    }
    CP_COMMIT();

    int tiles = (N + 63) >> 6;
    for (int t = blockIdx.x; t < tiles; t += gridDim.x) {
        int a0 = t * 64;
        __syncthreads();
        for (int i = tid; i < 64 * 32; i += 256) {
            int r = i >> 5, u = i & 31;
            int n = a0 + r; if (n >= N) n = N - 1;
            cpa16(Xs + r * L2KP + u * 8, g_h1h + (size_t)n * 256 + u * 8);
        }
        CP_COMMIT(); CP_WAIT0();
        __syncthreads();

        float acc[2][4][4];
        #pragma unroll
        for (int mt = 0; mt < 2; mt++)
            #pragma unroll
            for (int nt = 0; nt < 4; nt++)
                #pragma unroll
                for (int e = 0; e < 4; e++) acc[mt][nt][e] = 0.f;

        #pragma unroll 2
        for (int kg = 0; kg < 256; kg += 16) {
            uint32_t A[2][4];
            #pragma unroll
            for (int mt = 0; mt < 2; mt++) {
                int row = 32 * wm + 16 * mt + gid;
                A[mt][0] = h2u(&Xs[row * L2KP + kg + tig * 2]);
                A[mt][1] = h2u(&Xs[(row + 8) * L2KP + kg + tig * 2]);
                A[mt][2] = h2u(&Xs[row * L2KP + kg + tig * 2 + 8]);
                A[mt][3] = h2u(&Xs[(row + 8) * L2KP + kg + tig * 2 + 8]);
            }
            #pragma unroll
            for (int nt = 0; nt < 4; nt++) {
                int nn = 32 * wn + 8 * nt + gid;
                uint32_t B[2];
                B[0] = h2u(&W[nn * L2KP + kg + tig * 2]);
                B[1] = h2u(&W[nn * L2KP + kg + tig * 2 + 8]);
                mma_f16(acc[0][nt], A[0], B);
                mma_f16(acc[1][nt], A[1], B);
            }
        }

        #pragma unroll
        for (int mt = 0; mt < 2; mt++) {
            int row0 = 32 * wm + 16 * mt + gid;
            int n0 = a0 + row0, n1 = n0 + 8;
            #pragma unroll
            for (int nt = 0; nt < 4; nt++) {
                int col = 32 * wn + 8 * nt + 2 * tig;
                float bb0 = b2[col], bb1 = b2[col + 1];
                if (n0 < N)
                    *reinterpret_cast<__half2*>(&g_h2h[(size_t)n0 * 128 + col]) =
                        __floats2half2_rn(gelu_exact(acc[mt][nt][0] + bb0),
                                          gelu_exact(acc[mt][nt][1] + bb1));
                if (n1 < N)
                    *reinterpret_cast<__half2*>(&g_h2h[(size_t)n1 * 128 + col]) =
                        __floats2half2_rn(gelu_exact(acc[mt][nt][2] + bb0),
                                          gelu_exact(acc[mt][nt][3] + bb1));
            }
        }
    }
}

// ---------------------------------------------------------------------------
// Launch 6: Layer 3 (128 -> 130, linear) + output scatter, fp16. (unchanged)
// ---------------------------------------------------------------------------
#define L3KP 136
#define L3_OX (136 * L3KP)
#define L3_SMEM ((L3_OX + 64 * L3KP) * 2)

__global__ void __launch_bounds__(256, 2) k_l3(const float* __restrict__ b3,
                                               float* __restrict__ out, int N) {
    extern __shared__ __half smh[];
    __half* W  = smh;
    __half* Xs = smh + L3_OX;
    int tid = threadIdx.x;
    int lane = tid & 31, warp = tid >> 5;
    int gid = lane >> 2, tig = lane & 3;
    int wm = warp >> 2, wn = warp & 3;

    for (int i = tid; i < 136 * 16; i += 256) {
        int r = i >> 4, u = i & 15;
        cpa16(W + r * L3KP + u * 8, g_w3h + (size_t)r * 128 + u * 8);
    }
    CP_COMMIT();

    size_t dq_off = (size_t)N * 128;
    size_t f_off = dq_off + (size_t)N;
    int tiles = (N + 63) >> 6;
    for (int t = blockIdx.x; t < tiles; t += gridDim.x) {
        int a0 = t * 64;
        __syncthreads();
        for (int i = tid; i < 64 * 16; i += 256) {
            int r = i >> 4, u = i & 15;
            int n = a0 + r; if (n >= N) n = N - 1;
            cpa16(Xs + r * L3KP + u * 8, g_h2h + (size_t)n * 128 + u * 8);
        }
        CP_COMMIT(); CP_WAIT0();
        __syncthreads();

        float acc[2][5][4];
        #pragma unroll
        for (int mt = 0; mt < 2; mt++)
            #pragma unroll
            for (int nt = 0; nt < 5; nt++)
                #pragma unroll
                for (int e = 0; e < 4; e++) acc[mt][nt][e] = 0.f;

        #pragma unroll
        for (int kg = 0; kg < 128; kg += 16) {
            uint32_t A[2][4];
            #pragma unroll
            for (int mt = 0; mt < 2; mt++) {
                int row = 32 * wm + 16 * mt + gid;
                A[mt][0] = h2u(&Xs[row * L3KP + kg + tig * 2]);
                A[mt][1] = h2u(&Xs[(row + 8) * L3KP + kg + tig * 2]);
                A[mt][2] = h2u(&Xs[row * L3KP + kg + tig * 2 + 8]);
                A[mt][3] = h2u(&Xs[(row + 8) * L3KP + kg + tig * 2 + 8]);
            }
            #pragma unroll
            for (int nt = 0; nt < 5; nt++) {
                int u = 5 * wn + nt;
                if (u >= 17) break;
                int nn = 8 * u + gid;
                uint32_t B[2];
                B[0] = h2u(&W[nn * L3KP + kg + tig * 2]);
                B[1] = h2u(&W[nn * L3KP + kg + tig * 2 + 8]);
                mma_f16(acc[0][nt], A[0], B);
                mma_f16(acc[1][nt], A[1], B);
            }
        }

        #pragma unroll
        for (int mt = 0; mt < 2; mt++) {
            #pragma unroll
            for (int nt = 0; nt < 5; nt++) {
                int u = 5 * wn + nt;
                if (u >= 17) break;
                #pragma unroll
                for (int e = 0; e < 4; e++) {
                    int row = 32 * wm + 16 * mt + gid + ((e >> 1) ? 8 : 0);
                    int j = 8 * u + 2 * tig + (e & 1);
                    int n = a0 + row;
                    if (n >= N || j >= 130) continue;
                    float v = acc[mt][nt][e] + b3[j];
                    if (j == 0)      out[dq_off + n] = v;
                    else if (j == 1) out[f_off + n] = v;
                    else             out[(size_t)n * 128 + (j - 2)] = v;
                }
            }
        }
    }
}

// ---------------------------------------------------------------------------
extern "C" void kernel_launch(void* const* d_in, const int* in_sizes, int n_in,
                              void* d_out, int out_size) {
    const float* emb  = (const float*)d_in[0];
    const float* q    = (const float*)d_in[1];
    const int*   pidx = (const int*)d_in[2];
    const float* gs   = (const float*)d_in[3];
    const float* gv   = (const float*)d_in[4];
    const float* agh  = (const float*)d_in[5];
    const float* Wgf  = (const float*)d_in[6];
    const float* W1   = (const float*)d_in[7];
    const float* b1   = (const float*)d_in[8];
    const float* W2   = (const float*)d_in[9];
    const float* b2   = (const float*)d_in[10];
    const float* W3   = (const float*)d_in[11];
    const float* b3   = (const float*)d_in[12];
    float* out = (float*)d_out;

    int N = in_sizes[0] / 128;
    int P = in_sizes[2] / 2;
    if (N > NMAX) N = NMAX;
    const int* idxj = pidx + P;

    // 1: conversions + zero accumulators
    int cvt_tot = CVT_W + N * 128 + N * 16;
    k_cvt<<<(cvt_tot + 255) / 256, 256>>>(agh, W1, W2, W3, emb, N);

    // 2: pair scatter
    long long Q = (long long)P * 16;
    k_scatter<<<(int)((Q + 255) / 256), 256>>>(idxj, gs, gv, P);

    // 3: fused GEMM-M + assemble (fp16)
    cudaFuncSetAttribute(k_gemm_assemble, cudaFuncAttributeMaxDynamicSharedMemorySize, GA_SMEM);
    k_gemm_assemble<<<(N + 31) / 32, 256, GA_SMEM>>>(q, Wgf, N);

    // 4 (profiled): layer 1 fp16
    cudaFuncSetAttribute(k_l1, cudaFuncAttributeMaxDynamicSharedMemorySize, L1_SMEM);
    k_l1<<<148, 256, L1_SMEM>>>(b1, N);

    // 5: layer 2 fp16
    cudaFuncSetAttribute(k_l2, cudaFuncAttributeMaxDynamicSharedMemorySize, L2_SMEM);
    k_l2<<<296, 256, L2_SMEM>>>(b2, N);

    // 6: layer 3 fp16 + output scatter
    cudaFuncSetAttribute(k_l3, cudaFuncAttributeMaxDynamicSharedMemorySize, L3_SMEM);
    k_l3<<<296, 256, L3_SMEM>>>(b3, out, N);
}

// round 13
// speedup vs baseline: 1.2488x; 1.0211x over previous
#include <cuda_runtime.h>
#include <cuda_fp16.h>
#include <math.h>
#include <stdint.h>

// N=50000, P=1.6M, F=128, G=16, H=32, HID1=256, HID2=128, IN=288 (vec_q==0 dropped)
#define NMAX 50000

__device__ float  g_acc[NMAX * 64];             // [n][0:16]=Gsum, [16:64]=GVsum(d,g)
__device__ __half g_msgh[(size_t)NMAX * 288];   // MLP input fp16
__device__ __half g_h1h[(size_t)NMAX * 256];    // layer1 activations fp16
__device__ __half g_embh[(size_t)NMAX * 128];   // emb fp16
__device__ __half g_aghh[512 * 128];            // agh^T fp16 [n=512][k=128]
__device__ __half g_w1h[256 * 288];             // W1^T fp16 [n][k]
__device__ __half g_w2h[128 * 256];             // W2^T fp16 [n][k]
__device__ __half g_w3h[136 * 128];             // W3^T fp16 [n][k], n padded

__device__ __forceinline__ float gelu_exact(float x) {
    return 0.5f * x * (1.0f + erff(x * 0.70710678118654752f));
}
__device__ __forceinline__ void mma_f16(float d[4], const uint32_t a[4],
                                        const uint32_t b[2]) {
    asm volatile(
        "mma.sync.aligned.m16n8k16.row.col.f32.f16.f16.f32 "
        "{%0,%1,%2,%3}, {%4,%5,%6,%7}, {%8,%9}, {%0,%1,%2,%3};"
        : "+f"(d[0]), "+f"(d[1]), "+f"(d[2]), "+f"(d[3])
        : "r"(a[0]), "r"(a[1]), "r"(a[2]), "r"(a[3]), "r"(b[0]), "r"(b[1]));
}
__device__ __forceinline__ uint32_t h2u(const __half* p) {
    return *reinterpret_cast<const uint32_t*>(p);
}
__device__ __forceinline__ void cpa16(void* s, const void* g) {
    uint32_t sp = (uint32_t)__cvta_generic_to_shared(s);
    asm volatile("cp.async.cg.shared.global [%0], [%1], 16;" :: "r"(sp), "l"(g));
}
#define CP_COMMIT() asm volatile("cp.async.commit_group;" ::: "memory")
#define CP_WAIT1()  asm volatile("cp.async.wait_group 1;" ::: "memory")
#define CP_WAIT0()  asm volatile("cp.async.wait_group 0;" ::: "memory")

// ---------------------------------------------------------------------------
// Launch 1: conversions — agh^T fp16, W1/W2/W3^T fp16, emb fp16, zero g_acc.
// ---------------------------------------------------------------------------
#define CVT_W (512 * 128 + 256 * 288 + 128 * 256 + 136 * 128)
__global__ void k_cvt(const float* __restrict__ agh, const float* __restrict__ W1,
                      const float* __restrict__ W2, const float* __restrict__ W3,
                      const float* __restrict__ emb, int N) {
    int i = blockIdx.x * blockDim.x + threadIdx.x;
    if (i < 512 * 128) {
        int n = i >> 7, k = i & 127;
        g_aghh[i] = __float2half(agh[(size_t)k * 512 + n]);
        return;
    }
    i -= 512 * 128;
    if (i < 256 * 288) {
        int n = i / 288, k = i - n * 288;
        g_w1h[i] = __float2half(W1[(size_t)k * 256 + n]);
        return;
    }
    i -= 256 * 288;
    if (i < 128 * 256) {
        int n = i >> 8, k = i & 255;
        g_w2h[i] = __float2half(W2[(size_t)k * 128 + n]);
        return;
    }
    i -= 128 * 256;
    if (i < 136 * 128) {
        int n = i >> 7, k = i & 127;
        g_w3h[i] = (n < 130) ? __float2half(W3[(size_t)k * 130 + n]) : __float2half(0.f);
        return;
    }
    i -= 136 * 128;
    if (i < N * 128) { g_embh[i] = __float2half(emb[i]); return; }
    i -= N * 128;
    if (i < N * 16)
        reinterpret_cast<float4*>(g_acc)[i] = make_float4(0.f, 0.f, 0.f, 0.f);
}

// ---------------------------------------------------------------------------
// Launch 2: pair scatter (unchanged, LTS-RMW bound ~96us)
// ---------------------------------------------------------------------------
__global__ void k_scatter(const int* __restrict__ idxj, const float* __restrict__ gs,
                          const float* __restrict__ gv, int P) {
    long long q = (long long)blockIdx.x * blockDim.x + threadIdx.x;
    long long total = (long long)P * 16;
    if (q >= total) return;
    int p = (int)(q >> 4);
    int c = (int)(q & 15);
    int n = idxj[p];
    float4 v;
    float* dst;
    if (c < 4) {
        v = *reinterpret_cast<const float4*>(gs + (size_t)p * 16 + c * 4);
        dst = g_acc + (size_t)n * 64 + c * 4;
    } else {
        v = *reinterpret_cast<const float4*>(gv + (size_t)p * 48 + (c - 4) * 4);
        dst = g_acc + (size_t)n * 64 + 16 + (c - 4) * 4;
    }
    asm volatile("red.global.add.v4.f32 [%0], {%1,%2,%3,%4};"
                 :: "l"(dst), "f"(v.x), "f"(v.y), "f"(v.z), "f"(v.w)
                 : "memory");
}

// ---------------------------------------------------------------------------
// Launch 3: fused GEMM-M + assemble, 64 atoms/CTA, fp16 MMA + fp16 Ms overlay.
// smem 123904 B, 1 CTA/SM. 4 k-chunks of 32 double-buffered.
// ---------------------------------------------------------------------------
#define GXP 136                 // Xsh stride (halves)
#define GBP 40                  // weight chunk stride (halves): 32 + 8
#define GMP 520                 // Ms stride (halves)
#define GA_XS_B 0               // 64*136*2 = 17408
#define GA_SA_B 17408           // 64*64*4  = 16384
#define GA_WG_B 33792           // 16*128*4 = 8192
#define GA_WB_B 41984           // Wb0 512*40*2 = 40960
#define GA_WB1_B 82944          // Wb1 40960 -> ends 123904
#define GA_SMEM 123904

__global__ void __launch_bounds__(256, 1) k_gemm_assemble(
    const float* __restrict__ q, const float* __restrict__ Wgf, int N) {
    extern __shared__ char smraw[];
    __half* Xsh  = reinterpret_cast<__half*>(smraw + GA_XS_B);
    float*  sa   = reinterpret_cast<float*>(smraw + GA_SA_B);
    float*  Wgfs = reinterpret_cast<float*>(smraw + GA_WG_B);
    __half* Wb0  = reinterpret_cast<__half*>(smraw + GA_WB_B);
    __half* Wb1  = reinterpret_cast<__half*>(smraw + GA_WB1_B);
    __half* Msh  = reinterpret_cast<__half*>(smraw + GA_WB_B);   // overlay post-MMA
    int a0 = blockIdx.x * 64;
    int tid = threadIdx.x;
    int lane = tid & 31, wn = tid >> 5;    // 8 warps x 64 cols
    int gid = lane >> 2, tig = lane & 3;

    // stage Xs (emb fp16): 64 rows x 16 cpa16
    for (int i = tid; i < 64 * 16; i += 256) {
        int r = i >> 4, u = i & 15;
        int n = a0 + r; if (n >= N) n = N - 1;
        cpa16(Xsh + r * GXP + u * 8, g_embh + (size_t)n * 128 + u * 8);
    }
    // sa (fp32)
    for (int i = tid; i < 64 * 16; i += 256) {
        int r = i >> 4, c4 = i & 15;
        int n = a0 + r; if (n >= N) n = N - 1;
        cpa16(sa + r * 64 + c4 * 4, g_acc + (size_t)n * 64 + c4 * 4);
    }
    // Wgf (fp32)
    for (int i = tid; i < 16 * 32; i += 256) {
        cpa16(Wgfs + i * 4, Wgf + i * 4);
    }
    // chunk 0/1: 512 n-rows x 32 k halves (4 cpa16/row)
    for (int i = tid; i < 512 * 4; i += 256) {
        int r = i >> 2, u = i & 3;
        cpa16(Wb0 + r * GBP + u * 8, g_aghh + (size_t)r * 128 + u * 8);
    }
    CP_COMMIT();
    for (int i = tid; i < 512 * 4; i += 256) {
        int r = i >> 2, u = i & 3;
        cpa16(Wb1 + r * GBP + u * 8, g_aghh + (size_t)r * 128 + 32 + u * 8);
    }
    CP_COMMIT();

    float acc[4][8][4];
    #pragma unroll
    for (int mt = 0; mt < 4; mt++)
        #pragma unroll
        for (int nt = 0; nt < 8; nt++)
            #pragma unroll
            for (int e = 0; e < 4; e++) acc[mt][nt][e] = 0.f;

    for (int c = 0; c < 4; c++) {
        CP_WAIT1();
        __syncthreads();
        __half* wb = (c & 1) ? Wb1 : Wb0;
        #pragma unroll
        for (int ks = 0; ks < 32; ks += 16) {
            int kg = c * 32 + ks;
            uint32_t A[4][4];
            #pragma unroll
            for (int mt = 0; mt < 4; mt++) {
                int row = 16 * mt + gid;
                A[mt][0] = h2u(&Xsh[row * GXP + kg + tig * 2]);
                A[mt][1] = h2u(&Xsh[(row + 8) * GXP + kg + tig * 2]);
                A[mt][2] = h2u(&Xsh[row * GXP + kg + tig * 2 + 8]);
                A[mt][3] = h2u(&Xsh[(row + 8) * GXP + kg + tig * 2 + 8]);
            }
            #pragma unroll
            for (int nt = 0; nt < 8; nt++) {
                int nn = 64 * wn + 8 * nt + gid;
                uint32_t B[2];
                B[0] = h2u(&wb[nn * GBP + ks + tig * 2]);
                B[1] = h2u(&wb[nn * GBP + ks + tig * 2 + 8]);
                #pragma unroll
                for (int mt = 0; mt < 4; mt++) mma_f16(acc[mt][nt], A[mt], B);
            }
        }
        __syncthreads();
        if (c + 2 < 4) {
            __half* dst = (c & 1) ? Wb1 : Wb0;
            for (int i = tid; i < 512 * 4; i += 256) {
                int r = i >> 2, u = i & 3;
                cpa16(dst + r * GBP + u * 8,
                      g_aghh + (size_t)r * 128 + (c + 2) * 32 + u * 8);
            }
        }
        CP_COMMIT();
    }

    // epilogue: acc -> Msh (fp16 overlay on dead weight buffers)
    #pragma unroll
    for (int mt = 0; mt < 4; mt++) {
        int r0 = 16 * mt + gid;
        #pragma unroll
        for (int nt = 0; nt < 8; nt++) {
            int col = 64 * wn + 8 * nt + 2 * tig;
            *reinterpret_cast<__half2*>(&Msh[r0 * GMP + col]) =
                __floats2half2_rn(acc[mt][nt][0], acc[mt][nt][1]);
            *reinterpret_cast<__half2*>(&Msh[(r0 + 8) * GMP + col]) =
                __floats2half2_rn(acc[mt][nt][2], acc[mt][nt][3]);
        }
    }
    __syncthreads();

    // mapped = Gsum . W_gf[:,f]; rad_emb = emb*mapped; rad_q = q*mapped
    // 2 features per thread -> half2 stores
    for (int idx = tid; idx < 64 * 64; idx += 256) {
        int r = idx >> 6, f2 = idx & 63;
        int n = a0 + r;
        if (n >= N) continue;
        int f = 2 * f2;
        float m0 = 0.f, m1 = 0.f;
        #pragma unroll
        for (int g = 0; g < 16; g++) {
            float s = sa[r * 64 + g];
            m0 += s * Wgfs[g * 128 + f];
            m1 += s * Wgfs[g * 128 + f + 1];
        }
        float e0 = __half2float(Xsh[r * GXP + f]);
        float e1 = __half2float(Xsh[r * GXP + f + 1]);
        float qq = q[n];
        __half* msg = g_msgh + (size_t)n * 288;
        *reinterpret_cast<__half2*>(&msg[f])       = __floats2half2_rn(e0 * m0, e1 * m1);
        *reinterpret_cast<__half2*>(&msg[160 + f]) = __floats2half2_rn(qq * m0, qq * m1);
    }
    // vec_emb[h] = safe_norm over d of sum_g GVsum[d,g]*M[g*32+h]
    for (int idx = tid; idx < 64 * 32; idx += 256) {
        int r = idx >> 5, h = idx & 31;
        int n = a0 + r;
        if (n >= N) continue;
        float v0 = 0.f, v1 = 0.f, v2 = 0.f;
        #pragma unroll
        for (int g = 0; g < 16; g++) {
            float Mv = __half2float(Msh[r * GMP + g * 32 + h]);
            v0 += sa[r * 64 + 16 + g] * Mv;
            v1 += sa[r * 64 + 32 + g] * Mv;
            v2 += sa[r * 64 + 48 + g] * Mv;
        }
        float sq = v0 * v0 + v1 * v1 + v2 * v2;
        g_msgh[(size_t)n * 288 + 128 + h] = __float2half((sq > 0.f) ? sqrtf(sq) : 0.f);
    }
}

// ---------------------------------------------------------------------------
// Launch 4 (PROFILED): Layer 1 (288 -> 256, gelu), fp16, 128-atom tiles.
// W1^T fully resident. smem 227328 B, 1 CTA/SM, grid 148.
// ---------------------------------------------------------------------------
#define L1KP 296
#define L1_OX (256 * L1KP)
#define L1_SMEM ((L1_OX + 128 * L1KP) * 2)

__global__ void __launch_bounds__(256, 1) k_l1(const float* __restrict__ b1, int N) {
    extern __shared__ __half smh[];
    __half* W  = smh;
    __half* Xs = smh + L1_OX;
    int tid = threadIdx.x;
    int lane = tid & 31, warp = tid >> 5;
    int gid = lane >> 2, tig = lane & 3;
    int wm = warp >> 2, wn = warp & 3;   // 2m x 4n; warp tile 64 rows x 64 cols

    for (int i = tid; i < 256 * 36; i += 256) {
        int r = i / 36, u = i - r * 36;
        cpa16(W + r * L1KP + u * 8, g_w1h + (size_t)r * 288 + u * 8);
    }
    CP_COMMIT();

    int tiles = (N + 127) >> 7;
    for (int t = blockIdx.x; t < tiles; t += gridDim.x) {
        int a0 = t * 128;
        __syncthreads();
        for (int i = tid; i < 128 * 36; i += 256) {
            int r = i / 36, u = i - r * 36;
            int n = a0 + r; if (n >= N) n = N - 1;
            cpa16(Xs + r * L1KP + u * 8, g_msgh + (size_t)n * 288 + u * 8);
        }
        CP_COMMIT(); CP_WAIT0();
        __syncthreads();

        float acc[4][8][4];
        #pragma unroll
        for (int mt = 0; mt < 4; mt++)
            #pragma unroll
            for (int nt = 0; nt < 8; nt++)
                #pragma unroll
                for (int e = 0; e < 4; e++) acc[mt][nt][e] = 0.f;

        #pragma unroll 2
        for (int kg = 0; kg < 288; kg += 16) {
            uint32_t A[4][4];
            #pragma unroll
            for (int mt = 0; mt < 4; mt++) {
                int row = 64 * wm + 16 * mt + gid;
                A[mt][0] = h2u(&Xs[row * L1KP + kg + tig * 2]);
                A[mt][1] = h2u(&Xs[(row + 8) * L1KP + kg + tig * 2]);
                A[mt][2] = h2u(&Xs[row * L1KP + kg + tig * 2 + 8]);
                A[mt][3] = h2u(&Xs[(row + 8) * L1KP + kg + tig * 2 + 8]);
            }
            #pragma unroll
            for (int nt = 0; nt < 8; nt++) {
                int nn = 64 * wn + 8 * nt + gid;
                uint32_t B[2];
                B[0] = h2u(&W[nn * L1KP + kg + tig * 2]);
                B[1] = h2u(&W[nn * L1KP + kg + tig * 2 + 8]);
                #pragma unroll
                for (int mt = 0; mt < 4; mt++) mma_f16(acc[mt][nt], A[mt], B);
            }
        }

        #pragma unroll
        for (int mt = 0; mt < 4; mt++) {
            int row0 = 64 * wm + 16 * mt + gid;
            int n0 = a0 + row0, n1 = n0 + 8;
            #pragma unroll
            for (int nt = 0; nt < 8; nt++) {
                int col = 64 * wn + 8 * nt + 2 * tig;
                float bb0 = b1[col], bb1 = b1[col + 1];
                if (n0 < N)
                    *reinterpret_cast<__half2*>(&g_h1h[(size_t)n0 * 256 + col]) =
                        __floats2half2_rn(gelu_exact(acc[mt][nt][0] + bb0),
                                          gelu_exact(acc[mt][nt][1] + bb1));
                if (n1 < N)
                    *reinterpret_cast<__half2*>(&g_h1h[(size_t)n1 * 256 + col]) =
                        __floats2half2_rn(gelu_exact(acc[mt][nt][2] + bb0),
                                          gelu_exact(acc[mt][nt][3] + bb1));
            }
        }
    }
}

// ---------------------------------------------------------------------------
// Launch 5: merged Layers 2+3 (256->128 gelu -> 130 linear + scatter).
// W2 & W3 resident; H2 lives in smem only. smem 155776 B, grid 148.
// ---------------------------------------------------------------------------
#define L2KP 264
#define L3KP 136
#define M23_W2 0
#define M23_W3 (128 * L2KP)                   // 33792 halves
#define M23_XS (M23_W3 + 136 * L3KP)          // 52288
#define M23_H2 (M23_XS + 64 * L2KP)           // 69184
#define M23_SMEM ((M23_H2 + 64 * L3KP) * 2)   // 155776 B

__global__ void __launch_bounds__(256, 1) k_l23(const float* __restrict__ b2,
                                                const float* __restrict__ b3,
                                                float* __restrict__ out, int N) {
    extern __shared__ __half smh[];
    __half* W2 = smh + M23_W2;
    __half* W3 = smh + M23_W3;
    __half* Xs = smh + M23_XS;
    __half* H2 = smh + M23_H2;
    int tid = threadIdx.x;
    int lane = tid & 31, warp = tid >> 5;
    int gid = lane >> 2, tig = lane & 3;
    int wm = warp >> 2, wn = warp & 3;

    for (int i = tid; i < 128 * 32; i += 256) {
        int r = i >> 5, u = i & 31;
        cpa16(W2 + r * L2KP + u * 8, g_w2h + (size_t)r * 256 + u * 8);
    }
    for (int i = tid; i < 136 * 16; i += 256) {
        int r = i >> 4, u = i & 15;
        cpa16(W3 + r * L3KP + u * 8, g_w3h + (size_t)r * 128 + u * 8);
    }
    CP_COMMIT();

    size_t dq_off = (size_t)N * 128;
    size_t f_off = dq_off + (size_t)N;
    int tiles = (N + 63) >> 6;
    for (int t = blockIdx.x; t < tiles; t += gridDim.x) {
        int a0 = t * 64;
        __syncthreads();
        for (int i = tid; i < 64 * 32; i += 256) {
            int r = i >> 5, u = i & 31;
            int n = a0 + r; if (n >= N) n = N - 1;
            cpa16(Xs + r * L2KP + u * 8, g_h1h + (size_t)n * 256 + u * 8);
        }
        CP_COMMIT(); CP_WAIT0();
        __syncthreads();

        // ---- layer 2: 256 -> 128, gelu, into smem H2 ----
        float acc[2][4][4];
        #pragma unroll
        for (int mt = 0; mt < 2; mt++)
            #pragma unroll
            for (int nt = 0; nt < 4; nt++)
                #pragma unroll
                for (int e = 0; e < 4; e++) acc[mt][nt][e] = 0.f;

        #pragma unroll 2
        for (int kg = 0; kg < 256; kg += 16) {
            uint32_t A[2][4];
            #pragma unroll
            for (int mt = 0; mt < 2; mt++) {
                int row = 32 * wm + 16 * mt + gid;
                A[mt][0] = h2u(&Xs[row * L2KP + kg + tig * 2]);
                A[mt][1] = h2u(&Xs[(row + 8) * L2KP + kg + tig * 2]);
                A[mt][2] = h2u(&Xs[row * L2KP + kg + tig * 2 + 8]);
                A[mt][3] = h2u(&Xs[(row + 8) * L2KP + kg + tig * 2 + 8]);
            }
            #pragma unroll
            for (int nt = 0; nt < 4; nt++) {
                int nn = 32 * wn + 8 * nt + gid;
                uint32_t B[2];
                B[0] = h2u(&W2[nn * L2KP + kg + tig * 2]);
                B[1] = h2u(&W2[nn * L2KP + kg + tig * 2 + 8]);
                mma_f16(acc[0][nt], A[0], B);
                mma_f16(acc[1][nt], A[1], B);
            }
        }
        #pragma unroll
        for (int mt = 0; mt < 2; mt++) {
            int row0 = 32 * wm + 16 * mt + gid;
            #pragma unroll
            for (int nt = 0; nt < 4; nt++) {
                int col = 32 * wn + 8 * nt + 2 * tig;
                float bb0 = b2[col], bb1 = b2[col + 1];
                *reinterpret_cast<__half2*>(&H2[row0 * L3KP + col]) =
                    __floats2half2_rn(gelu_exact(acc[mt][nt][0] + bb0),
                                      gelu_exact(acc[mt][nt][1] + bb1));
                *reinterpret_cast<__half2*>(&H2[(row0 + 8) * L3KP + col]) =
                    __floats2half2_rn(gelu_exact(acc[mt][nt][2] + bb0),
                                      gelu_exact(acc[mt][nt][3] + bb1));
            }
        }
        __syncthreads();

        // ---- layer 3: 128 -> 130, linear, scatter to out ----
        float acc3[2][5][4];
        #pragma unroll
        for (int mt = 0; mt < 2; mt++)
            #pragma unroll
            for (int nt = 0; nt < 5; nt++)
                #pragma unroll
                for (int e = 0; e < 4; e++) acc3[mt][nt][e] = 0.f;

        #pragma unroll
        for (int kg = 0; kg < 128; kg += 16) {
            uint32_t A[2][4];
            #pragma unroll
            for (int mt = 0; mt < 2; mt++) {
                int row = 32 * wm + 16 * mt + gid;
                A[mt][0] = h2u(&H2[row * L3KP + kg + tig * 2]);
                A[mt][1] = h2u(&H2[(row + 8) * L3KP + kg + tig * 2]);
                A[mt][2] = h2u(&H2[row * L3KP + kg + tig * 2 + 8]);
                A[mt][3] = h2u(&H2[(row + 8) * L3KP + kg + tig * 2 + 8]);
            }
            #pragma unroll
            for (int nt = 0; nt < 5; nt++) {
                int u = 5 * wn + nt;
                if (u >= 17) break;
                int nn = 8 * u + gid;
                uint32_t B[2];
                B[0] = h2u(&W3[nn * L3KP + kg + tig * 2]);
                B[1] = h2u(&W3[nn * L3KP + kg + tig * 2 + 8]);
                mma_f16(acc3[0][nt], A[0], B);
                mma_f16(acc3[1][nt], A[1], B);
            }
        }

        #pragma unroll
        for (int mt = 0; mt < 2; mt++) {
            #pragma unroll
            for (int nt = 0; nt < 5; nt++) {
                int u = 5 * wn + nt;
                if (u >= 17) break;
                #pragma unroll
                for (int e = 0; e < 4; e++) {
                    int row = 32 * wm + 16 * mt + gid + ((e >> 1) ? 8 : 0);
                    int j = 8 * u + 2 * tig + (e & 1);
                    int n = a0 + row;
                    if (n >= N || j >= 130) continue;
                    float v = acc3[mt][nt][e] + b3[j];
                    if (j == 0)      out[dq_off + n] = v;
                    else if (j == 1) out[f_off + n] = v;
                    else             out[(size_t)n * 128 + (j - 2)] = v;
                }
            }
        }
    }
}

// ---------------------------------------------------------------------------
extern "C" void kernel_launch(void* const* d_in, const int* in_sizes, int n_in,
                              void* d_out, int out_size) {
    const float* emb  = (const float*)d_in[0];
    const float* q    = (const float*)d_in[1];
    const int*   pidx = (const int*)d_in[2];
    const float* gs   = (const float*)d_in[3];
    const float* gv   = (const float*)d_in[4];
    const float* agh  = (const float*)d_in[5];
    const float* Wgf  = (const float*)d_in[6];
    const float* W1   = (const float*)d_in[7];
    const float* b1   = (const float*)d_in[8];
    const float* W2   = (const float*)d_in[9];
    const float* b2   = (const float*)d_in[10];
    const float* W3   = (const float*)d_in[11];
    const float* b3   = (const float*)d_in[12];
    float* out = (float*)d_out;

    int N = in_sizes[0] / 128;
    int P = in_sizes[2] / 2;
    if (N > NMAX) N = NMAX;
    const int* idxj = pidx + P;

    // 1: conversions + zero accumulators
    int cvt_tot = CVT_W + N * 128 + N * 16;
    k_cvt<<<(cvt_tot + 255) / 256, 256>>>(agh, W1, W2, W3, emb, N);

    // 2: pair scatter
    long long Q = (long long)P * 16;
    k_scatter<<<(int)((Q + 255) / 256), 256>>>(idxj, gs, gv, P);

    // 3: fused GEMM-M + assemble (64 atoms/CTA, fp16 Ms)
    cudaFuncSetAttribute(k_gemm_assemble, cudaFuncAttributeMaxDynamicSharedMemorySize, GA_SMEM);
    k_gemm_assemble<<<(N + 63) / 64, 256, GA_SMEM>>>(q, Wgf, N);

    // 4 (profiled): layer 1 fp16, 128-atom tiles
    cudaFuncSetAttribute(k_l1, cudaFuncAttributeMaxDynamicSharedMemorySize, L1_SMEM);
    k_l1<<<148, 256, L1_SMEM>>>(b1, N);

    // 5: merged layers 2+3
    cudaFuncSetAttribute(k_l23, cudaFuncAttributeMaxDynamicSharedMemorySize, M23_SMEM);
    k_l23<<<148, 256, M23_SMEM>>>(b2, b3, out, N);
}

// round 14
// speedup vs baseline: 1.2774x; 1.0229x over previous
#include <cuda_runtime.h>
#include <cuda_fp16.h>
#include <math.h>
#include <stdint.h>

// N=50000, P=1.6M, F=128, G=16, H=32, HID1=256, HID2=128, IN=288 (vec_q==0 dropped)
#define NMAX 50000

__device__ float  g_acc[NMAX * 64];             // [n][0:16]=Gsum, [16:64]=GVsum(d,g)
__device__ __half g_msgh[(size_t)NMAX * 288];   // MLP input fp16
__device__ __half g_h1h[(size_t)NMAX * 256];    // layer1 activations fp16
__device__ __half g_embh[(size_t)NMAX * 128];   // emb fp16
__device__ __half g_aghh[512 * 128];            // agh^T fp16 [n=512][k=128]
__device__ __half g_w1h[256 * 288];             // W1^T fp16 [n][k]
__device__ __half g_w2h[128 * 256];             // W2^T fp16 [n][k]
__device__ __half g_w3h[136 * 128];             // W3^T fp16 [n][k], n padded

__device__ __forceinline__ float gelu_exact(float x) {
    return 0.5f * x * (1.0f + erff(x * 0.70710678118654752f));
}
__device__ __forceinline__ void mma_f16(float d[4], const uint32_t a[4],
                                        const uint32_t b[2]) {
    asm volatile(
        "mma.sync.aligned.m16n8k16.row.col.f32.f16.f16.f32 "
        "{%0,%1,%2,%3}, {%4,%5,%6,%7}, {%8,%9}, {%0,%1,%2,%3};"
        : "+f"(d[0]), "+f"(d[1]), "+f"(d[2]), "+f"(d[3])
        : "r"(a[0]), "r"(a[1]), "r"(a[2]), "r"(a[3]), "r"(b[0]), "r"(b[1]));
}
__device__ __forceinline__ uint32_t h2u(const __half* p) {
    return *reinterpret_cast<const uint32_t*>(p);
}
__device__ __forceinline__ void cpa16(void* s, const void* g) {
    uint32_t sp = (uint32_t)__cvta_generic_to_shared(s);
    asm volatile("cp.async.cg.shared.global [%0], [%1], 16;" :: "r"(sp), "l"(g));
}
#define CP_COMMIT() asm volatile("cp.async.commit_group;" ::: "memory")
#define CP_WAIT1()  asm volatile("cp.async.wait_group 1;" ::: "memory")
#define CP_WAIT0()  asm volatile("cp.async.wait_group 0;" ::: "memory")

// ---------------------------------------------------------------------------
// Launch 1: zero pair accumulators (must precede scatter)
// ---------------------------------------------------------------------------
__global__ void k_zero(int N) {
    int i = blockIdx.x * blockDim.x + threadIdx.x;
    if (i < N * 16)
        reinterpret_cast<float4*>(g_acc)[i] = make_float4(0.f, 0.f, 0.f, 0.f);
}

// ---------------------------------------------------------------------------
// Launch 2: MERGED scatter + conversions. Blocks < SB do the pair scatter;
// the rest do fp16/layout conversions (fills scatter's bandwidth shadow).
// ---------------------------------------------------------------------------
#define CVT_W (512 * 128 + 256 * 288 + 128 * 256 + 136 * 128)
__global__ void k_scatter_cvt(const int* __restrict__ idxj, const float* __restrict__ gs,
                              const float* __restrict__ gv, int P, int SB,
                              const float* __restrict__ agh, const float* __restrict__ W1,
                              const float* __restrict__ W2, const float* __restrict__ W3,
                              const float* __restrict__ emb, int N) {
    if (blockIdx.x < SB) {
        long long qq = (long long)blockIdx.x * blockDim.x + threadIdx.x;
        long long total = (long long)P * 16;
        if (qq >= total) return;
        int p = (int)(qq >> 4);
        int c = (int)(qq & 15);
        int n = idxj[p];
        float4 v;
        float* dst;
        if (c < 4) {
            v = *reinterpret_cast<const float4*>(gs + (size_t)p * 16 + c * 4);
            dst = g_acc + (size_t)n * 64 + c * 4;
        } else {
            v = *reinterpret_cast<const float4*>(gv + (size_t)p * 48 + (c - 4) * 4);
            dst = g_acc + (size_t)n * 64 + 16 + (c - 4) * 4;
        }
        asm volatile("red.global.add.v4.f32 [%0], {%1,%2,%3,%4};"
                     :: "l"(dst), "f"(v.x), "f"(v.y), "f"(v.z), "f"(v.w)
                     : "memory");
        return;
    }
    int i = (blockIdx.x - SB) * blockDim.x + threadIdx.x;
    if (i < 512 * 128) {                        // agh^T [n=512][k=128]
        int n = i >> 7, k = i & 127;
        g_aghh[i] = __float2half(agh[(size_t)k * 512 + n]);
        return;
    }
    i -= 512 * 128;
    if (i < 256 * 288) {                        // W1^T
        int n = i / 288, k = i - n * 288;
        g_w1h[i] = __float2half(W1[(size_t)k * 256 + n]);
        return;
    }
    i -= 256 * 288;
    if (i < 128 * 256) {                        // W2^T
        int n = i >> 8, k = i & 255;
        g_w2h[i] = __float2half(W2[(size_t)k * 128 + n]);
        return;
    }
    i -= 128 * 256;
    if (i < 136 * 128) {                        // W3^T padded
        int n = i >> 7, k = i & 127;
        g_w3h[i] = (n < 130) ? __float2half(W3[(size_t)k * 130 + n]) : __float2half(0.f);
        return;
    }
    i -= 136 * 128;
    if (i < N * 128) g_embh[i] = __float2half(emb[i]);
}

// ---------------------------------------------------------------------------
// Launch 3: fused GEMM-M + assemble, 64 atoms/CTA, 512 threads (16 warps).
// fp16 MMA, fp16 Ms overlay, double-buffered agh chunks. smem 123904 B.
// ---------------------------------------------------------------------------
#define GXP 136
#define GBP 40
#define GMP 520
#define GA_XS_B 0
#define GA_SA_B 17408
#define GA_WG_B 33792
#define GA_WB_B 41984
#define GA_WB1_B 82944
#define GA_SMEM 123904

__global__ void __launch_bounds__(512, 1) k_gemm_assemble(
    const float* __restrict__ q, const float* __restrict__ Wgf, int N) {
    extern __shared__ char smraw[];
    __half* Xsh  = reinterpret_cast<__half*>(smraw + GA_XS_B);
    float*  sa   = reinterpret_cast<float*>(smraw + GA_SA_B);
    float*  Wgfs = reinterpret_cast<float*>(smraw + GA_WG_B);
    __half* Wb0  = reinterpret_cast<__half*>(smraw + GA_WB_B);
    __half* Wb1  = reinterpret_cast<__half*>(smraw + GA_WB1_B);
    __half* Msh  = reinterpret_cast<__half*>(smraw + GA_WB_B);   // overlay post-MMA
    int a0 = blockIdx.x * 64;
    int tid = threadIdx.x;
    int lane = tid & 31, warp = tid >> 5;
    int gid = lane >> 2, tig = lane & 3;
    int wm = warp >> 3, wn = warp & 7;    // 2m x 8n: warp = 32 rows x 64 cols

    for (int i = tid; i < 64 * 16; i += 512) {
        int r = i >> 4, u = i & 15;
        int n = a0 + r; if (n >= N) n = N - 1;
        cpa16(Xsh + r * GXP + u * 8, g_embh + (size_t)n * 128 + u * 8);
    }
    for (int i = tid; i < 64 * 16; i += 512) {
        int r = i >> 4, c4 = i & 15;
        int n = a0 + r; if (n >= N) n = N - 1;
        cpa16(sa + r * 64 + c4 * 4, g_acc + (size_t)n * 64 + c4 * 4);
    }
    for (int i = tid; i < 16 * 32; i += 512) {
        cpa16(Wgfs + i * 4, Wgf + i * 4);
    }
    for (int i = tid; i < 512 * 4; i += 512) {
        int r = i >> 2, u = i & 3;
        cpa16(Wb0 + r * GBP + u * 8, g_aghh + (size_t)r * 128 + u * 8);
    }
    CP_COMMIT();
    for (int i = tid; i < 512 * 4; i += 512) {
        int r = i >> 2, u = i & 3;
        cpa16(Wb1 + r * GBP + u * 8, g_aghh + (size_t)r * 128 + 32 + u * 8);
    }
    CP_COMMIT();

    float acc[2][8][4];
    #pragma unroll
    for (int mt = 0; mt < 2; mt++)
        #pragma unroll
        for (int nt = 0; nt < 8; nt++)
            #pragma unroll
            for (int e = 0; e < 4; e++) acc[mt][nt][e] = 0.f;

    for (int c = 0; c < 4; c++) {
        CP_WAIT1();
        __syncthreads();
        __half* wb = (c & 1) ? Wb1 : Wb0;
        #pragma unroll
        for (int ks = 0; ks < 32; ks += 16) {
            int kg = c * 32 + ks;
            uint32_t A[2][4];
            #pragma unroll
            for (int mt = 0; mt < 2; mt++) {
                int row = 32 * wm + 16 * mt + gid;
                A[mt][0] = h2u(&Xsh[row * GXP + kg + tig * 2]);
                A[mt][1] = h2u(&Xsh[(row + 8) * GXP + kg + tig * 2]);
                A[mt][2] = h2u(&Xsh[row * GXP + kg + tig * 2 + 8]);
                A[mt][3] = h2u(&Xsh[(row + 8) * GXP + kg + tig * 2 + 8]);
            }
            #pragma unroll
            for (int nt = 0; nt < 8; nt++) {
                int nn = 64 * wn + 8 * nt + gid;
                uint32_t B[2];
                B[0] = h2u(&wb[nn * GBP + ks + tig * 2]);
                B[1] = h2u(&wb[nn * GBP + ks + tig * 2 + 8]);
                mma_f16(acc[0][nt], A[0], B);
                mma_f16(acc[1][nt], A[1], B);
            }
        }
        __syncthreads();
        if (c + 2 < 4) {
            __half* dst = (c & 1) ? Wb1 : Wb0;
            for (int i = tid; i < 512 * 4; i += 512) {
                int r = i >> 2, u = i & 3;
                cpa16(dst + r * GBP + u * 8,
                      g_aghh + (size_t)r * 128 + (c + 2) * 32 + u * 8);
            }
        }
        CP_COMMIT();
    }

    // epilogue: acc -> Msh (fp16 overlay)
    #pragma unroll
    for (int mt = 0; mt < 2; mt++) {
        int r0 = 32 * wm + 16 * mt + gid;
        #pragma unroll
        for (int nt = 0; nt < 8; nt++) {
            int col = 64 * wn + 8 * nt + 2 * tig;
            *reinterpret_cast<__half2*>(&Msh[r0 * GMP + col]) =
                __floats2half2_rn(acc[mt][nt][0], acc[mt][nt][1]);
            *reinterpret_cast<__half2*>(&Msh[(r0 + 8) * GMP + col]) =
                __floats2half2_rn(acc[mt][nt][2], acc[mt][nt][3]);
        }
    }
    __syncthreads();

    for (int idx = tid; idx < 64 * 64; idx += 512) {
        int r = idx >> 6, f2 = idx & 63;
        int n = a0 + r;
        if (n >= N) continue;
        int f = 2 * f2;
        float m0 = 0.f, m1 = 0.f;
        #pragma unroll
        for (int g = 0; g < 16; g++) {
            float s = sa[r * 64 + g];
            m0 += s * Wgfs[g * 128 + f];
            m1 += s * Wgfs[g * 128 + f + 1];
        }
        float e0 = __half2float(Xsh[r * GXP + f]);
        float e1 = __half2float(Xsh[r * GXP + f + 1]);
        float qq = q[n];
        __half* msg = g_msgh + (size_t)n * 288;
        *reinterpret_cast<__half2*>(&msg[f])       = __floats2half2_rn(e0 * m0, e1 * m1);
        *reinterpret_cast<__half2*>(&msg[160 + f]) = __floats2half2_rn(qq * m0, qq * m1);
    }
    for (int idx = tid; idx < 64 * 32; idx += 512) {
        int r = idx >> 5, h = idx & 31;
        int n = a0 + r;
        if (n >= N) continue;
        float v0 = 0.f, v1 = 0.f, v2 = 0.f;
        #pragma unroll
        for (int g = 0; g < 16; g++) {
            float Mv = __half2float(Msh[r * GMP + g * 32 + h]);
            v0 += sa[r * 64 + 16 + g] * Mv;
            v1 += sa[r * 64 + 32 + g] * Mv;
            v2 += sa[r * 64 + 48 + g] * Mv;
        }
        float sq = v0 * v0 + v1 * v1 + v2 * v2;
        g_msgh[(size_t)n * 288 + 128 + h] = __float2half((sq > 0.f) ? sqrtf(sq) : 0.f);
    }
}

// ---------------------------------------------------------------------------
// Launch 4 (PROFILED): Layer 1 (288 -> 256, gelu), fp16, 128-atom tiles,
// 512 threads (16 warps = 4m x 4n). W1^T fully resident. smem 227328 B.
// ---------------------------------------------------------------------------
#define L1KP 296
#define L1_OX (256 * L1KP)
#define L1_SMEM ((L1_OX + 128 * L1KP) * 2)

__global__ void __launch_bounds__(512, 1) k_l1(const float* __restrict__ b1, int N) {
    extern __shared__ __half smh[];
    __half* W  = smh;
    __half* Xs = smh + L1_OX;
    int tid = threadIdx.x;
    int lane = tid & 31, warp = tid >> 5;
    int gid = lane >> 2, tig = lane & 3;
    int wm = warp >> 2, wn = warp & 3;   // 4m x 4n; warp tile 32 rows x 64 cols

    for (int i = tid; i < 256 * 36; i += 512) {
        int r = i / 36, u = i - r * 36;
        cpa16(W + r * L1KP + u * 8, g_w1h + (size_t)r * 288 + u * 8);
    }
    CP_COMMIT();

    int tiles = (N + 127) >> 7;
    for (int t = blockIdx.x; t < tiles; t += gridDim.x) {
        int a0 = t * 128;
        __syncthreads();
        for (int i = tid; i < 128 * 36; i += 512) {
            int r = i / 36, u = i - r * 36;
            int n = a0 + r; if (n >= N) n = N - 1;
            cpa16(Xs + r * L1KP + u * 8, g_msgh + (size_t)n * 288 + u * 8);
        }
        CP_COMMIT(); CP_WAIT0();
        __syncthreads();

        float acc[2][8][4];
        #pragma unroll
        for (int mt = 0; mt < 2; mt++)
            #pragma unroll
            for (int nt = 0; nt < 8; nt++)
                #pragma unroll
                for (int e = 0; e < 4; e++) acc[mt][nt][e] = 0.f;

        #pragma unroll 2
        for (int kg = 0; kg < 288; kg += 16) {
            uint32_t A[2][4];
            #pragma unroll
            for (int mt = 0; mt < 2; mt++) {
                int row = 32 * wm + 16 * mt + gid;
                A[mt][0] = h2u(&Xs[row * L1KP + kg + tig * 2]);
                A[mt][1] = h2u(&Xs[(row + 8) * L1KP + kg + tig * 2]);
                A[mt][2] = h2u(&Xs[row * L1KP + kg + tig * 2 + 8]);
                A[mt][3] = h2u(&Xs[(row + 8) * L1KP + kg + tig * 2 + 8]);
            }
            #pragma unroll
            for (int nt = 0; nt < 8; nt++) {
                int nn = 64 * wn + 8 * nt + gid;
                uint32_t B[2];
                B[0] = h2u(&W[nn * L1KP + kg + tig * 2]);
                B[1] = h2u(&W[nn * L1KP + kg + tig * 2 + 8]);
                mma_f16(acc[0][nt], A[0], B);
                mma_f16(acc[1][nt], A[1], B);
            }
        }

        #pragma unroll
        for (int mt = 0; mt < 2; mt++) {
            int row0 = 32 * wm + 16 * mt + gid;
            int n0 = a0 + row0, n1 = n0 + 8;
            #pragma unroll
            for (int nt = 0; nt < 8; nt++) {
                int col = 64 * wn + 8 * nt + 2 * tig;
                float bb0 = b1[col], bb1 = b1[col + 1];
                if (n0 < N)
                    *reinterpret_cast<__half2*>(&g_h1h[(size_t)n0 * 256 + col]) =
                        __floats2half2_rn(gelu_exact(acc[mt][nt][0] + bb0),
                                          gelu_exact(acc[mt][nt][1] + bb1));
                if (n1 < N)
                    *reinterpret_cast<__half2*>(&g_h1h[(size_t)n1 * 256 + col]) =
                        __floats2half2_rn(gelu_exact(acc[mt][nt][2] + bb0),
                                          gelu_exact(acc[mt][nt][3] + bb1));
            }
        }
    }
}

// ---------------------------------------------------------------------------
// Launch 5: merged Layers 2+3 (256->128 gelu -> 130 linear + scatter),
// 512 threads (16 warps). W2 & W3 resident; H2 smem-only. smem 155776 B.
// ---------------------------------------------------------------------------
#define L2KP 264
#define L3KP 136
#define M23_W2 0
#define M23_W3 (128 * L2KP)
#define M23_XS (M23_W3 + 136 * L3KP)
#define M23_H2 (M23_XS + 64 * L2KP)
#define M23_SMEM ((M23_H2 + 64 * L3KP) * 2)

__global__ void __launch_bounds__(512, 1) k_l23(const float* __restrict__ b2,
                                                const float* __restrict__ b3,
                                                float* __restrict__ out, int N) {
    extern __shared__ __half smh[];
    __half* W2 = smh + M23_W2;
    __half* W3 = smh + M23_W3;
    __half* Xs = smh + M23_XS;
    __half* H2 = smh + M23_H2;
    int tid = threadIdx.x;
    int lane = tid & 31, warp = tid >> 5;
    int gid = lane >> 2, tig = lane & 3;
    int wm = warp >> 3, wn = warp & 7;   // layer2: 2m x 8n

    for (int i = tid; i < 128 * 32; i += 512) {
        int r = i >> 5, u = i & 31;
        cpa16(W2 + r * L2KP + u * 8, g_w2h + (size_t)r * 256 + u * 8);
    }
    for (int i = tid; i < 136 * 16; i += 512) {
        int r = i >> 4, u = i & 15;
        cpa16(W3 + r * L3KP + u * 8, g_w3h + (size_t)r * 128 + u * 8);
    }
    CP_COMMIT();

    size_t dq_off = (size_t)N * 128;
    size_t f_off = dq_off + (size_t)N;
    int tiles = (N + 63) >> 6;
    for (int t = blockIdx.x; t < tiles; t += gridDim.x) {
        int a0 = t * 64;
        __syncthreads();
        for (int i = tid; i < 64 * 32; i += 512) {
            int r = i >> 5, u = i & 31;
            int n = a0 + r; if (n >= N) n = N - 1;
            cpa16(Xs + r * L2KP + u * 8, g_h1h + (size_t)n * 256 + u * 8);
        }
        CP_COMMIT(); CP_WAIT0();
        __syncthreads();

        // ---- layer 2: 64x128, warp = 32 rows x 16 cols ----
        float acc[2][2][4];
        #pragma unroll
        for (int mt = 0; mt < 2; mt++)
            #pragma unroll
            for (int nt = 0; nt < 2; nt++)
                #pragma unroll
                for (int e = 0; e < 4; e++) acc[mt][nt][e] = 0.f;

        #pragma unroll 2
        for (int kg = 0; kg < 256; kg += 16) {
            uint32_t A[2][4];
            #pragma unroll
            for (int mt = 0; mt < 2; mt++) {
                int row = 32 * wm + 16 * mt + gid;
                A[mt][0] = h2u(&Xs[row * L2KP + kg + tig * 2]);
                A[mt][1] = h2u(&Xs[(row + 8) * L2KP + kg + tig * 2]);
                A[mt][2] = h2u(&Xs[row * L2KP + kg + tig * 2 + 8]);
                A[mt][3] = h2u(&Xs[(row + 8) * L2KP + kg + tig * 2 + 8]);
            }
            #pragma unroll
            for (int nt = 0; nt < 2; nt++) {
                int nn = 16 * wn + 8 * nt + gid;
                uint32_t B[2];
                B[0] = h2u(&W2[nn * L2KP + kg + tig * 2]);
                B[1] = h2u(&W2[nn * L2KP + kg + tig * 2 + 8]);
                mma_f16(acc[0][nt], A[0], B);
                mma_f16(acc[1][nt], A[1], B);
            }
        }
        #pragma unroll
        for (int mt = 0; mt < 2; mt++) {
            int row0 = 32 * wm + 16 * mt + gid;
            #pragma unroll
            for (int nt = 0; nt < 2; nt++) {
                int col = 16 * wn + 8 * nt + 2 * tig;
                float bb0 = b2[col], bb1 = b2[col + 1];
                *reinterpret_cast<__half2*>(&H2[row0 * L3KP + col]) =
                    __floats2half2_rn(gelu_exact(acc[mt][nt][0] + bb0),
                                      gelu_exact(acc[mt][nt][1] + bb1));
                *reinterpret_cast<__half2*>(&H2[(row0 + 8) * L3KP + col]) =
                    __floats2half2_rn(gelu_exact(acc[mt][nt][2] + bb0),
                                      gelu_exact(acc[mt][nt][3] + bb1));
            }
        }
        __syncthreads();

        // ---- layer 3: 68 warp-tiles (4m x 17n) over 16 warps ----
        float d3[5][4];
        #pragma unroll
        for (int tt = 0; tt < 5; tt++)
            #pragma unroll
            for (int e = 0; e < 4; e++) d3[tt][e] = 0.f;

        #pragma unroll
        for (int tt = 0; tt < 5; tt++) {
            int tw = warp + 16 * tt;
            if (tw >= 68) break;
            int m0 = 16 * (tw & 3), n0 = 8 * (tw >> 2);
            #pragma unroll
            for (int kg = 0; kg < 128; kg += 16) {
                uint32_t A[4], B[2];
                A[0] = h2u(&H2[(m0 + gid) * L3KP + kg + tig * 2]);
                A[1] = h2u(&H2[(m0 + 8 + gid) * L3KP + kg + tig * 2]);
                A[2] = h2u(&H2[(m0 + gid) * L3KP + kg + tig * 2 + 8]);
                A[3] = h2u(&H2[(m0 + 8 + gid) * L3KP + kg + tig * 2 + 8]);
                B[0] = h2u(&W3[(n0 + gid) * L3KP + kg + tig * 2]);
                B[1] = h2u(&W3[(n0 + gid) * L3KP + kg + tig * 2 + 8]);
                mma_f16(d3[tt], A, B);
            }
        }

        #pragma unroll
        for (int tt = 0; tt < 5; tt++) {
            int tw = warp + 16 * tt;
            if (tw >= 68) break;
            int m0 = 16 * (tw & 3), n0 = 8 * (tw >> 2);
            #pragma unroll
            for (int e = 0; e < 4; e++) {
                int row = m0 + gid + ((e >> 1) ? 8 : 0);
                int j = n0 + 2 * tig + (e & 1);
                int n = a0 + row;
                if (n >= N || j >= 130) continue;
                float v = d3[tt][e] + b3[j];
                if (j == 0)      out[dq_off + n] = v;
                else if (j == 1) out[f_off + n] = v;
                else             out[(size_t)n * 128 + (j - 2)] = v;
            }
        }
    }
}

// ---------------------------------------------------------------------------
extern "C" void kernel_launch(void* const* d_in, const int* in_sizes, int n_in,
                              void* d_out, int out_size) {
    const float* emb  = (const float*)d_in[0];
    const float* q    = (const float*)d_in[1];
    const int*   pidx = (const int*)d_in[2];
    const float* gs   = (const float*)d_in[3];
    const float* gv   = (const float*)d_in[4];
    const float* agh  = (const float*)d_in[5];
    const float* Wgf  = (const float*)d_in[6];
    const float* W1   = (const float*)d_in[7];
    const float* b1   = (const float*)d_in[8];
    const float* W2   = (const float*)d_in[9];
    const float* b2   = (const float*)d_in[10];
    const float* W3   = (const float*)d_in[11];
    const float* b3   = (const float*)d_in[12];
    float* out = (float*)d_out;

    int N = in_sizes[0] / 128;
    int P = in_sizes[2] / 2;
    if (N > NMAX) N = NMAX;
    const int* idxj = pidx + P;

    // 1: zero accumulators
    k_zero<<<(N * 16 + 255) / 256, 256>>>(N);

    // 2: merged scatter + conversions
    long long Q = (long long)P * 16;
    int SB = (int)((Q + 255) / 256);
    int CB = (CVT_W + N * 128 + 255) / 256;
    k_scatter_cvt<<<SB + CB, 256>>>(idxj, gs, gv, P, SB, agh, W1, W2, W3, emb, N);

    // 3: fused GEMM-M + assemble (512 threads)
    cudaFuncSetAttribute(k_gemm_assemble, cudaFuncAttributeMaxDynamicSharedMemorySize, GA_SMEM);
    k_gemm_assemble<<<(N + 63) / 64, 512, GA_SMEM>>>(q, Wgf, N);

    // 4 (profiled): layer 1 (512 threads, 128-atom tiles)
    cudaFuncSetAttribute(k_l1, cudaFuncAttributeMaxDynamicSharedMemorySize, L1_SMEM);
    k_l1<<<148, 512, L1_SMEM>>>(b1, N);

    // 5: merged layers 2+3 (512 threads)
    cudaFuncSetAttribute(k_l23, cudaFuncAttributeMaxDynamicSharedMemorySize, M23_SMEM);
    k_l23<<<148, 512, M23_SMEM>>>(b2, b3, out, N);
}

// round 15
// speedup vs baseline: 1.3072x; 1.0233x over previous
#include <cuda_runtime.h>
#include <cuda_fp16.h>
#include <math.h>
#include <stdint.h>

// N=50000, P=1.6M, F=128, G=16, H=32, HID1=256, HID2=128, IN=288 (vec_q==0 dropped)
#define NMAX 50000

__device__ float  g_acc[NMAX * 64];             // [n][0:16]=Gsum, [16:64]=GVsum(d,g)
__device__ __half g_msgh[(size_t)NMAX * 288];   // MLP input fp16
__device__ __half g_h1h[(size_t)NMAX * 256];    // layer1 activations fp16
__device__ __half g_embh[(size_t)NMAX * 128];   // emb fp16
__device__ __half g_aghh[512 * 128];            // agh^T fp16 [n=512][k=128]
__device__ __half g_w1h[256 * 288];             // W1^T fp16 [n][k]
__device__ __half g_w2h[128 * 256];             // W2^T fp16 [n][k]
__device__ __half g_w3h[136 * 128];             // W3^T fp16 [n][k], n padded

__device__ __forceinline__ float gelu_exact(float x) {
    return 0.5f * x * (1.0f + erff(x * 0.70710678118654752f));
}
__device__ __forceinline__ void mma_f16(float d[4], const uint32_t a[4],
                                        const uint32_t b[2]) {
    asm volatile(
        "mma.sync.aligned.m16n8k16.row.col.f32.f16.f16.f32 "
        "{%0,%1,%2,%3}, {%4,%5,%6,%7}, {%8,%9}, {%0,%1,%2,%3};"
        : "+f"(d[0]), "+f"(d[1]), "+f"(d[2]), "+f"(d[3])
        : "r"(a[0]), "r"(a[1]), "r"(a[2]), "r"(a[3]), "r"(b[0]), "r"(b[1]));
}
__device__ __forceinline__ uint32_t h2u(const __half* p) {
    return *reinterpret_cast<const uint32_t*>(p);
}
__device__ __forceinline__ void cpa16(void* s, const void* g) {
    uint32_t sp = (uint32_t)__cvta_generic_to_shared(s);
    asm volatile("cp.async.cg.shared.global [%0], [%1], 16;" :: "r"(sp), "l"(g));
}
#define CP_COMMIT() asm volatile("cp.async.commit_group;" ::: "memory")
#define CP_WAIT1()  asm volatile("cp.async.wait_group 1;" ::: "memory")
#define CP_WAIT0()  asm volatile("cp.async.wait_group 0;" ::: "memory")

// ---------------------------------------------------------------------------
// Launch 1: zero pair accumulators
// ---------------------------------------------------------------------------
__global__ void k_zero(int N) {
    int i = blockIdx.x * blockDim.x + threadIdx.x;
    if (i < N * 16)
        reinterpret_cast<float4*>(g_acc)[i] = make_float4(0.f, 0.f, 0.f, 0.f);
}

// ---------------------------------------------------------------------------
// Launch 2: MERGED scatter (2 quads/thread, MLP=2) + fp16 conversions.
// ---------------------------------------------------------------------------
#define CVT_W (512 * 128 + 256 * 288 + 128 * 256 + 136 * 128)
__global__ void k_scatter_cvt(const int* __restrict__ idxj, const float* __restrict__ gs,
                              const float* __restrict__ gv, int P, int SB,
                              const float* __restrict__ agh, const float* __restrict__ W1,
                              const float* __restrict__ W2, const float* __restrict__ W3,
                              const float* __restrict__ emb, int N) {
    if (blockIdx.x < SB) {
        long long total = (long long)P * 16;
        long long q1 = (long long)blockIdx.x * 512 + threadIdx.x;
        long long q2 = q1 + 256;
        float4 v1, v2;
        float *d1 = 0, *d2 = 0;
        if (q1 < total) {
            int p = (int)(q1 >> 4), c = (int)(q1 & 15);
            int n = idxj[p];
            if (c < 4) {
                v1 = *reinterpret_cast<const float4*>(gs + (size_t)p * 16 + c * 4);
                d1 = g_acc + (size_t)n * 64 + c * 4;
            } else {
                v1 = *reinterpret_cast<const float4*>(gv + (size_t)p * 48 + (c - 4) * 4);
                d1 = g_acc + (size_t)n * 64 + 16 + (c - 4) * 4;
            }
        }
        if (q2 < total) {
            int p = (int)(q2 >> 4), c = (int)(q2 & 15);
            int n = idxj[p];
            if (c < 4) {
                v2 = *reinterpret_cast<const float4*>(gs + (size_t)p * 16 + c * 4);
                d2 = g_acc + (size_t)n * 64 + c * 4;
            } else {
                v2 = *reinterpret_cast<const float4*>(gv + (size_t)p * 48 + (c - 4) * 4);
                d2 = g_acc + (size_t)n * 64 + 16 + (c - 4) * 4;
            }
        }
        if (d1)
            asm volatile("red.global.add.v4.f32 [%0], {%1,%2,%3,%4};"
                         :: "l"(d1), "f"(v1.x), "f"(v1.y), "f"(v1.z), "f"(v1.w) : "memory");
        if (d2)
            asm volatile("red.global.add.v4.f32 [%0], {%1,%2,%3,%4};"
                         :: "l"(d2), "f"(v2.x), "f"(v2.y), "f"(v2.z), "f"(v2.w) : "memory");
        return;
    }
    int i = (blockIdx.x - SB) * blockDim.x + threadIdx.x;
    if (i < 512 * 128) {
        int n = i >> 7, k = i & 127;
        g_aghh[i] = __float2half(agh[(size_t)k * 512 + n]);
        return;
    }
    i -= 512 * 128;
    if (i < 256 * 288) {
        int n = i / 288, k = i - n * 288;
        g_w1h[i] = __float2half(W1[(size_t)k * 256 + n]);
        return;
    }
    i -= 256 * 288;
    if (i < 128 * 256) {
        int n = i >> 8, k = i & 255;
        g_w2h[i] = __float2half(W2[(size_t)k * 128 + n]);
        return;
    }
    i -= 128 * 256;
    if (i < 136 * 128) {
        int n = i >> 7, k = i & 127;
        g_w3h[i] = (n < 130) ? __float2half(W3[(size_t)k * 130 + n]) : __float2half(0.f);
        return;
    }
    i -= 136 * 128;
    if (i < N * 128) g_embh[i] = __float2half(emb[i]);
}

// ---------------------------------------------------------------------------
// Launch 3: fused GEMM-M + assemble, 64 atoms/CTA, 512 threads (unchanged R14)
// ---------------------------------------------------------------------------
#define GXP 136
#define GBP 40
#define GMP 520
#define GA_XS_B 0
#define GA_SA_B 17408
#define GA_WG_B 33792
#define GA_WB_B 41984
#define GA_WB1_B 82944
#define GA_SMEM 123904

__global__ void __launch_bounds__(512, 1) k_gemm_assemble(
    const float* __restrict__ q, const float* __restrict__ Wgf, int N) {
    extern __shared__ char smraw[];
    __half* Xsh  = reinterpret_cast<__half*>(smraw + GA_XS_B);
    float*  sa   = reinterpret_cast<float*>(smraw + GA_SA_B);
    float*  Wgfs = reinterpret_cast<float*>(smraw + GA_WG_B);
    __half* Wb0  = reinterpret_cast<__half*>(smraw + GA_WB_B);
    __half* Wb1  = reinterpret_cast<__half*>(smraw + GA_WB1_B);
    __half* Msh  = reinterpret_cast<__half*>(smraw + GA_WB_B);
    int a0 = blockIdx.x * 64;
    int tid = threadIdx.x;
    int lane = tid & 31, warp = tid >> 5;
    int gid = lane >> 2, tig = lane & 3;
    int wm = warp >> 3, wn = warp & 7;

    for (int i = tid; i < 64 * 16; i += 512) {
        int r = i >> 4, u = i & 15;
        int n = a0 + r; if (n >= N) n = N - 1;
        cpa16(Xsh + r * GXP + u * 8, g_embh + (size_t)n * 128 + u * 8);
    }
    for (int i = tid; i < 64 * 16; i += 512) {
        int r = i >> 4, c4 = i & 15;
        int n = a0 + r; if (n >= N) n = N - 1;
        cpa16(sa + r * 64 + c4 * 4, g_acc + (size_t)n * 64 + c4 * 4);
    }
    for (int i = tid; i < 16 * 32; i += 512) {
        cpa16(Wgfs + i * 4, Wgf + i * 4);
    }
    for (int i = tid; i < 512 * 4; i += 512) {
        int r = i >> 2, u = i & 3;
        cpa16(Wb0 + r * GBP + u * 8, g_aghh + (size_t)r * 128 + u * 8);
    }
    CP_COMMIT();
    for (int i = tid; i < 512 * 4; i += 512) {
        int r = i >> 2, u = i & 3;
        cpa16(Wb1 + r * GBP + u * 8, g_aghh + (size_t)r * 128 + 32 + u * 8);
    }
    CP_COMMIT();

    float acc[2][8][4];
    #pragma unroll
    for (int mt = 0; mt < 2; mt++)
        #pragma unroll
        for (int nt = 0; nt < 8; nt++)
            #pragma unroll
            for (int e = 0; e < 4; e++) acc[mt][nt][e] = 0.f;

    for (int c = 0; c < 4; c++) {
        CP_WAIT1();
        __syncthreads();
        __half* wb = (c & 1) ? Wb1 : Wb0;
        #pragma unroll
        for (int ks = 0; ks < 32; ks += 16) {
            int kg = c * 32 + ks;
            uint32_t A[2][4];
            #pragma unroll
            for (int mt = 0; mt < 2; mt++) {
                int row = 32 * wm + 16 * mt + gid;
                A[mt][0] = h2u(&Xsh[row * GXP + kg + tig * 2]);
                A[mt][1] = h2u(&Xsh[(row + 8) * GXP + kg + tig * 2]);
                A[mt][2] = h2u(&Xsh[row * GXP + kg + tig * 2 + 8]);
                A[mt][3] = h2u(&Xsh[(row + 8) * GXP + kg + tig * 2 + 8]);
            }
            #pragma unroll
            for (int nt = 0; nt < 8; nt++) {
                int nn = 64 * wn + 8 * nt + gid;
                uint32_t B[2];
                B[0] = h2u(&wb[nn * GBP + ks + tig * 2]);
                B[1] = h2u(&wb[nn * GBP + ks + tig * 2 + 8]);
                mma_f16(acc[0][nt], A[0], B);
                mma_f16(acc[1][nt], A[1], B);
            }
        }
        __syncthreads();
        if (c + 2 < 4) {
            __half* dst = (c & 1) ? Wb1 : Wb0;
            for (int i = tid; i < 512 * 4; i += 512) {
                int r = i >> 2, u = i & 3;
                cpa16(dst + r * GBP + u * 8,
                      g_aghh + (size_t)r * 128 + (c + 2) * 32 + u * 8);
            }
        }
        CP_COMMIT();
    }

    #pragma unroll
    for (int mt = 0; mt < 2; mt++) {
        int r0 = 32 * wm + 16 * mt + gid;
        #pragma unroll
        for (int nt = 0; nt < 8; nt++) {
            int col = 64 * wn + 8 * nt + 2 * tig;
            *reinterpret_cast<__half2*>(&Msh[r0 * GMP + col]) =
                __floats2half2_rn(acc[mt][nt][0], acc[mt][nt][1]);
            *reinterpret_cast<__half2*>(&Msh[(r0 + 8) * GMP + col]) =
                __floats2half2_rn(acc[mt][nt][2], acc[mt][nt][3]);
        }
    }
    __syncthreads();

    for (int idx = tid; idx < 64 * 64; idx += 512) {
        int r = idx >> 6, f2 = idx & 63;
        int n = a0 + r;
        if (n >= N) continue;
        int f = 2 * f2;
        float m0 = 0.f, m1 = 0.f;
        #pragma unroll
        for (int g = 0; g < 16; g++) {
            float s = sa[r * 64 + g];
            m0 += s * Wgfs[g * 128 + f];
            m1 += s * Wgfs[g * 128 + f + 1];
        }
        float e0 = __half2float(Xsh[r * GXP + f]);
        float e1 = __half2float(Xsh[r * GXP + f + 1]);
        float qq = q[n];
        __half* msg = g_msgh + (size_t)n * 288;
        *reinterpret_cast<__half2*>(&msg[f])       = __floats2half2_rn(e0 * m0, e1 * m1);
        *reinterpret_cast<__half2*>(&msg[160 + f]) = __floats2half2_rn(qq * m0, qq * m1);
    }
    for (int idx = tid; idx < 64 * 32; idx += 512) {
        int r = idx >> 5, h = idx & 31;
        int n = a0 + r;
        if (n >= N) continue;
        float v0 = 0.f, v1 = 0.f, v2 = 0.f;
        #pragma unroll
        for (int g = 0; g < 16; g++) {
            float Mv = __half2float(Msh[r * GMP + g * 32 + h]);
            v0 += sa[r * 64 + 16 + g] * Mv;
            v1 += sa[r * 64 + 32 + g] * Mv;
            v2 += sa[r * 64 + 48 + g] * Mv;
        }
        float sq = v0 * v0 + v1 * v1 + v2 * v2;
        g_msgh[(size_t)n * 288 + 128 + h] = __float2half((sq > 0.f) ? sqrtf(sq) : 0.f);
    }
}

// ---------------------------------------------------------------------------
// Launch 4 (PROFILED): Layer 1, fp16, 64-atom tiles DOUBLE-BUFFERED acts.
// W1^T resident. smem = 151552 + 2*37888 = 227328 B. 512 threads, grid 148.
// ---------------------------------------------------------------------------
#define L1KP 296
#define L1_W  0
#define L1_X0 (256 * L1KP)
#define L1_X1 (L1_X0 + 64 * L1KP)
#define L1_SMEM ((L1_X1 + 64 * L1KP) * 2)

__device__ __forceinline__ void l1_stage(__half* dst, int t, int N) {
    int a0 = t * 64;
    for (int i = threadIdx.x; i < 64 * 36; i += 512) {
        int r = i / 36, u = i - r * 36;
        int n = a0 + r; if (n >= N) n = N - 1;
        cpa16(dst + r * L1KP + u * 8, g_msgh + (size_t)n * 288 + u * 8);
    }
}

__global__ void __launch_bounds__(512, 1) k_l1(const float* __restrict__ b1, int N) {
    extern __shared__ __half smh[];
    __half* W  = smh + L1_W;
    __half* X0 = smh + L1_X0;
    __half* X1 = smh + L1_X1;
    int tid = threadIdx.x;
    int lane = tid & 31, warp = tid >> 5;
    int gid = lane >> 2, tig = lane & 3;
    int wm = warp >> 3, wn = warp & 7;   // 2m x 8n over 64 x 256

    for (int i = tid; i < 256 * 36; i += 512) {
        int r = i / 36, u = i - r * 36;
        cpa16(W + r * L1KP + u * 8, g_w1h + (size_t)r * 288 + u * 8);
    }
    CP_COMMIT();

    int tiles = (N + 63) >> 6;
    if (blockIdx.x < tiles) l1_stage(X0, blockIdx.x, N);
    CP_COMMIT();
    if (blockIdx.x + 148 < tiles) l1_stage(X1, blockIdx.x + 148, N);
    CP_COMMIT();

    int it = 0;
    for (int t = blockIdx.x; t < tiles; t += 148, it++) {
        CP_WAIT1();
        __syncthreads();
        __half* Xs = (it & 1) ? X1 : X0;
        int a0 = t * 64;

        float acc[2][4][4];
        #pragma unroll
        for (int mt = 0; mt < 2; mt++)
            #pragma unroll
            for (int nt = 0; nt < 4; nt++)
                #pragma unroll
                for (int e = 0; e < 4; e++) acc[mt][nt][e] = 0.f;

        #pragma unroll 2
        for (int kg = 0; kg < 288; kg += 16) {
            uint32_t A[2][4];
            #pragma unroll
            for (int mt = 0; mt < 2; mt++) {
                int row = 32 * wm + 16 * mt + gid;
                A[mt][0] = h2u(&Xs[row * L1KP + kg + tig * 2]);
                A[mt][1] = h2u(&Xs[(row + 8) * L1KP + kg + tig * 2]);
                A[mt][2] = h2u(&Xs[row * L1KP + kg + tig * 2 + 8]);
                A[mt][3] = h2u(&Xs[(row + 8) * L1KP + kg + tig * 2 + 8]);
            }
            #pragma unroll
            for (int nt = 0; nt < 4; nt++) {
                int nn = 32 * wn + 8 * nt + gid;
                uint32_t B[2];
                B[0] = h2u(&W[nn * L1KP + kg + tig * 2]);
                B[1] = h2u(&W[nn * L1KP + kg + tig * 2 + 8]);
                mma_f16(acc[0][nt], A[0], B);
                mma_f16(acc[1][nt], A[1], B);
            }
        }
        __syncthreads();   // all reads of Xs done before restage
        int tn = t + 2 * 148;
        if (tn < tiles) l1_stage(Xs, tn, N);
        CP_COMMIT();

        #pragma unroll
        for (int mt = 0; mt < 2; mt++) {
            int row0 = 32 * wm + 16 * mt + gid;
            int n0 = a0 + row0, n1 = n0 + 8;
            #pragma unroll
            for (int nt = 0; nt < 4; nt++) {
                int col = 32 * wn + 8 * nt + 2 * tig;
                float bb0 = b1[col], bb1 = b1[col + 1];
                if (n0 < N)
                    *reinterpret_cast<__half2*>(&g_h1h[(size_t)n0 * 256 + col]) =
                        __floats2half2_rn(gelu_exact(acc[mt][nt][0] + bb0),
                                          gelu_exact(acc[mt][nt][1] + bb1));
                if (n1 < N)
                    *reinterpret_cast<__half2*>(&g_h1h[(size_t)n1 * 256 + col]) =
                        __floats2half2_rn(gelu_exact(acc[mt][nt][2] + bb0),
                                          gelu_exact(acc[mt][nt][3] + bb1));
            }
        }
    }
}

// ---------------------------------------------------------------------------
// Launch 5: merged Layers 2+3, double-buffered acts. W2,W3 resident.
// smem = (33792 + 18496 + 2*16896 + 8704) * 2 = 189568 B. 512 threads.
// ---------------------------------------------------------------------------
#define L2KP 264
#define L3KP 136
#define M23_W2 0
#define M23_W3 (128 * L2KP)                   // 33792
#define M23_X0 (M23_W3 + 136 * L3KP)          // 52288
#define M23_X1 (M23_X0 + 64 * L2KP)           // 69184
#define M23_H2 (M23_X1 + 64 * L2KP)           // 86080
#define M23_SMEM ((M23_H2 + 64 * L3KP) * 2)   // 189568 B

__device__ __forceinline__ void l23_stage(__half* dst, int t, int N) {
    int a0 = t * 64;
    for (int i = threadIdx.x; i < 64 * 32; i += 512) {
        int r = i >> 5, u = i & 31;
        int n = a0 + r; if (n >= N) n = N - 1;
        cpa16(dst + r * L2KP + u * 8, g_h1h + (size_t)n * 256 + u * 8);
    }
}

__global__ void __launch_bounds__(512, 1) k_l23(const float* __restrict__ b2,
                                                const float* __restrict__ b3,
                                                float* __restrict__ out, int N) {
    extern __shared__ __half smh[];
    __half* W2 = smh + M23_W2;
    __half* W3 = smh + M23_W3;
    __half* X0 = smh + M23_X0;
    __half* X1 = smh + M23_X1;
    __half* H2 = smh + M23_H2;
    int tid = threadIdx.x;
    int lane = tid & 31, warp = tid >> 5;
    int gid = lane >> 2, tig = lane & 3;
    int wm = warp >> 3, wn = warp & 7;

    for (int i = tid; i < 128 * 32; i += 512) {
        int r = i >> 5, u = i & 31;
        cpa16(W2 + r * L2KP + u * 8, g_w2h + (size_t)r * 256 + u * 8);
    }
    for (int i = tid; i < 136 * 16; i += 512) {
        int r = i >> 4, u = i & 15;
        cpa16(W3 + r * L3KP + u * 8, g_w3h + (size_t)r * 128 + u * 8);
    }
    CP_COMMIT();

    int tiles = (N + 63) >> 6;
    if (blockIdx.x < tiles) l23_stage(X0, blockIdx.x, N);
    CP_COMMIT();
    if (blockIdx.x + 148 < tiles) l23_stage(X1, blockIdx.x + 148, N);
    CP_COMMIT();

    size_t dq_off = (size_t)N * 128;
    size_t f_off = dq_off + (size_t)N;
    int it = 0;
    for (int t = blockIdx.x; t < tiles; t += 148, it++) {
        CP_WAIT1();
        __syncthreads();
        __half* Xs = (it & 1) ? X1 : X0;
        int a0 = t * 64;

        // ---- layer 2: 64x128, warp = 32 rows x 16 cols ----
        float acc[2][2][4];
        #pragma unroll
        for (int mt = 0; mt < 2; mt++)
            #pragma unroll
            for (int nt = 0; nt < 2; nt++)
                #pragma unroll
                for (int e = 0; e < 4; e++) acc[mt][nt][e] = 0.f;

        #pragma unroll 2
        for (int kg = 0; kg < 256; kg += 16) {
            uint32_t A[2][4];
            #pragma unroll
            for (int mt = 0; mt < 2; mt++) {
                int row = 32 * wm + 16 * mt + gid;
                A[mt][0] = h2u(&Xs[row * L2KP + kg + tig * 2]);
                A[mt][1] = h2u(&Xs[(row + 8) * L2KP + kg + tig * 2]);
                A[mt][2] = h2u(&Xs[row * L2KP + kg + tig * 2 + 8]);
                A[mt][3] = h2u(&Xs[(row + 8) * L2KP + kg + tig * 2 + 8]);
            }
            #pragma unroll
            for (int nt = 0; nt < 2; nt++) {
                int nn = 16 * wn + 8 * nt + gid;
                uint32_t B[2];
                B[0] = h2u(&W2[nn * L2KP + kg + tig * 2]);
                B[1] = h2u(&W2[nn * L2KP + kg + tig * 2 + 8]);
                mma_f16(acc[0][nt], A[0], B);
                mma_f16(acc[1][nt], A[1], B);
            }
        }
        #pragma unroll
        for (int mt = 0; mt < 2; mt++) {
            int row0 = 32 * wm + 16 * mt + gid;
            #pragma unroll
            for (int nt = 0; nt < 2; nt++) {
                int col = 16 * wn + 8 * nt + 2 * tig;
                float bb0 = b2[col], bb1 = b2[col + 1];
                *reinterpret_cast<__half2*>(&H2[row0 * L3KP + col]) =
                    __floats2half2_rn(gelu_exact(acc[mt][nt][0] + bb0),
                                      gelu_exact(acc[mt][nt][1] + bb1));
                *reinterpret_cast<__half2*>(&H2[(row0 + 8) * L3KP + col]) =
                    __floats2half2_rn(gelu_exact(acc[mt][nt][2] + bb0),
                                      gelu_exact(acc[mt][nt][3] + bb1));
            }
        }
        __syncthreads();   // Xs reads done + H2 visible
        int tn = t + 2 * 148;
        if (tn < tiles) l23_stage(Xs, tn, N);
        CP_COMMIT();

        // ---- layer 3: 68 warp-tiles (4m x 17n) over 16 warps ----
        float d3[5][4];
        #pragma unroll
        for (int tt = 0; tt < 5; tt++)
            #pragma unroll
            for (int e = 0; e < 4; e++) d3[tt][e] = 0.f;

        #pragma unroll
        for (int tt = 0; tt < 5; tt++) {
            int tw = warp + 16 * tt;
            if (tw >= 68) break;
            int m0 = 16 * (tw & 3), n0 = 8 * (tw >> 2);
            #pragma unroll
            for (int kg = 0; kg < 128; kg += 16) {
                uint32_t A[4], B[2];
                A[0] = h2u(&H2[(m0 + gid) * L3KP + kg + tig * 2]);
                A[1] = h2u(&H2[(m0 + 8 + gid) * L3KP + kg + tig * 2]);
                A[2] = h2u(&H2[(m0 + gid) * L3KP + kg + tig * 2 + 8]);
                A[3] = h2u(&H2[(m0 + 8 + gid) * L3KP + kg + tig * 2 + 8]);
                B[0] = h2u(&W3[(n0 + gid) * L3KP + kg + tig * 2]);
                B[1] = h2u(&W3[(n0 + gid) * L3KP + kg + tig * 2 + 8]);
                mma_f16(d3[tt], A, B);
            }
        }

        #pragma unroll
        for (int tt = 0; tt < 5; tt++) {
            int tw = warp + 16 * tt;
            if (tw >= 68) break;
            int m0 = 16 * (tw & 3), n0 = 8 * (tw >> 2);
            #pragma unroll
            for (int e = 0; e < 4; e++) {
                int row = m0 + gid + ((e >> 1) ? 8 : 0);
                int j = n0 + 2 * tig + (e & 1);
                int n = a0 + row;
                if (n >= N || j >= 130) continue;
                float v = d3[tt][e] + b3[j];
                if (j == 0)      out[dq_off + n] = v;
                else if (j == 1) out[f_off + n] = v;
                else             out[(size_t)n * 128 + (j - 2)] = v;
            }
        }
    }
}

// ---------------------------------------------------------------------------
extern "C" void kernel_launch(void* const* d_in, const int* in_sizes, int n_in,
                              void* d_out, int out_size) {
    const float* emb  = (const float*)d_in[0];
    const float* q    = (const float*)d_in[1];
    const int*   pidx = (const int*)d_in[2];
    const float* gs   = (const float*)d_in[3];
    const float* gv   = (const float*)d_in[4];
    const float* agh  = (const float*)d_in[5];
    const float* Wgf  = (const float*)d_in[6];
    const float* W1   = (const float*)d_in[7];
    const float* b1   = (const float*)d_in[8];
    const float* W2   = (const float*)d_in[9];
    const float* b2   = (const float*)d_in[10];
    const float* W3   = (const float*)d_in[11];
    const float* b3   = (const float*)d_in[12];
    float* out = (float*)d_out;

    int N = in_sizes[0] / 128;
    int P = in_sizes[2] / 2;
    if (N > NMAX) N = NMAX;
    const int* idxj = pidx + P;

    // 1: zero accumulators
    k_zero<<<(N * 16 + 255) / 256, 256>>>(N);

    // 2: merged scatter (2 quads/thread) + conversions
    long long Q = (long long)P * 16;
    int SB = (int)((Q + 511) / 512);
    int CB = (CVT_W + N * 128 + 255) / 256;
    k_scatter_cvt<<<SB + CB, 256>>>(idxj, gs, gv, P, SB, agh, W1, W2, W3, emb, N);

    // 3: fused GEMM-M + assemble
    cudaFuncSetAttribute(k_gemm_assemble, cudaFuncAttributeMaxDynamicSharedMemorySize, GA_SMEM);
    k_gemm_assemble<<<(N + 63) / 64, 512, GA_SMEM>>>(q, Wgf, N);

    // 4 (profiled): layer 1, double-buffered acts
    cudaFuncSetAttribute(k_l1, cudaFuncAttributeMaxDynamicSharedMemorySize, L1_SMEM);
    k_l1<<<148, 512, L1_SMEM>>>(b1, N);

    // 5: merged layers 2+3, double-buffered acts
    cudaFuncSetAttribute(k_l23, cudaFuncAttributeMaxDynamicSharedMemorySize, M23_SMEM);
    k_l23<<<148, 512, M23_SMEM>>>(b2, b3, out, N);
}